// round 14
// baseline (speedup 1.0000x reference)
#include <cuda_runtime.h>
#include <cuda_fp16.h>
#include <cuda_fp8.h>

#define TT 256
#define CC 56
#define HH 1024
#define NBLK 148
#define NTHR 1024
#define NBGW 4704                /* bg warps: blocks 1..147 x 32 */
#define INV_WSCALE (1.0f/64.0f)

// ---------------- folded / quantized weights (built per launch) ----------------
__device__ __align__(16) __half  h_F[4][(size_t)4096*1024];   // F_{m->m+1} fp16
__device__ __align__(16) __half  h_F0[(size_t)4096*64];       // Wih0[:,:H]*W0
__device__ __align__(16) unsigned char w8_G[4][(size_t)4096*2048]; // [Wih[:,H:]|Whh] fp8
__device__ __align__(16) unsigned char w8_Gtop[(size_t)4096*1024]; // Whh_top fp8
__device__ __align__(16) __half  h_Vmid[(size_t)4*1024*1024];
__device__ __align__(16) __half  h_V1[(size_t)56*1024];
__device__ float d_gbase[5][4096];

// fp16 staging for the tensor-core fold GEMM
__device__ __align__(16) __half  h_A16[(size_t)4*4096*1024];
__device__ __align__(16) __half  h_BT[(size_t)4*1024*1024];

// ---------------- runtime state ------------------------------------------------
__device__ float g_z[5][4096];
__device__ float g_G[5][4096];
__device__ __align__(4) __half g_reconR[4][HH];
__device__ __align__(4) __half g_recon1[64];
__device__ float g_loss_parts[TT][5];
__device__ unsigned g_arrive[NBLK];

// ---------------- helpers ------------------------------------------------------
__device__ __forceinline__ float ldf(const float* p) { return __ldcg(p); }
__device__ __forceinline__ void  stf(float* p, float v) { __stcg(p, v); }
__device__ __forceinline__ float ldh(const __half* p) {
    unsigned short u = __ldcg(reinterpret_cast<const unsigned short*>(p));
    return __half2float(__ushort_as_half(u));
}
__device__ __forceinline__ void sth(__half* p, float v) {
    __stcg(reinterpret_cast<unsigned short*>(p), __half_as_ushort(__float2half_rn(v)));
}

__device__ __forceinline__ float warp_red(float v) {
#pragma unroll
    for (int o = 16; o; o >>= 1) v += __shfl_xor_sync(0xffffffffu, v, o);
    return v;
}

__device__ __forceinline__ __half2 cvt8(unsigned v16) {
    __half2_raw r = __nv_cvt_fp8x2_to_halfraw2((__nv_fp8x2_storage_t)v16, __NV_E4M3);
    return *reinterpret_cast<__half2*>(&r);
}
__device__ __forceinline__ float hsum(__half2 h) {
    float2 f = __half22float2(h);
    return f.x + f.y;
}

template<int NB>
__device__ __forceinline__ float dot8(const unsigned char* __restrict__ w,
                                      const __half* __restrict__ x, int lane) {
    float acc = 0.f;
#pragma unroll
    for (int it = 0; it < NB / 512; it++) {
        int c = it * 512 + lane * 16;
        uint4 wv  = *reinterpret_cast<const uint4*>(w + c);
        uint4 xv0 = *reinterpret_cast<const uint4*>(reinterpret_cast<const char*>(x) + 2 * c);
        uint4 xv1 = *reinterpret_cast<const uint4*>(reinterpret_cast<const char*>(x) + 2 * c + 16);
        const __half2* xa = reinterpret_cast<const __half2*>(&xv0);
        const __half2* xb = reinterpret_cast<const __half2*>(&xv1);
        __half2 s = __floats2half2_rn(0.f, 0.f);
        s = __hfma2(cvt8(wv.x & 0xffffu), xa[0], s);
        s = __hfma2(cvt8(wv.x >> 16),     xa[1], s);
        s = __hfma2(cvt8(wv.y & 0xffffu), xa[2], s);
        s = __hfma2(cvt8(wv.y >> 16),     xa[3], s);
        s = __hfma2(cvt8(wv.z & 0xffffu), xb[0], s);
        s = __hfma2(cvt8(wv.z >> 16),     xb[1], s);
        s = __hfma2(cvt8(wv.w & 0xffffu), xb[2], s);
        s = __hfma2(cvt8(wv.w >> 16),     xb[3], s);
        acc += hsum(s);
    }
    return acc;
}

template<int NB>
__device__ __forceinline__ float dot16(const __half* __restrict__ w,
                                       const __half* __restrict__ x, int lane) {
    float acc = 0.f;
#pragma unroll
    for (int it = 0; it < NB / 512; it++) {
        int c = it * 512 + lane * 16;
        uint4 wv = *reinterpret_cast<const uint4*>(reinterpret_cast<const char*>(w) + c);
        uint4 xv = *reinterpret_cast<const uint4*>(reinterpret_cast<const char*>(x) + c);
        const __half2* wa = reinterpret_cast<const __half2*>(&wv);
        const __half2* xa = reinterpret_cast<const __half2*>(&xv);
        __half2 s = __floats2half2_rn(0.f, 0.f);
        s = __hfma2(wa[0], xa[0], s);
        s = __hfma2(wa[1], xa[1], s);
        s = __hfma2(wa[2], xa[2], s);
        s = __hfma2(wa[3], xa[3], s);
        acc += hsum(s);
    }
    return acc;
}

__device__ __forceinline__ float dot56h(const __half* __restrict__ w,
                                        const float* __restrict__ x, int lane) {
    float acc = 0.f;
    if (lane < 28) {
        __half2 h = *reinterpret_cast<const __half2*>(w + lane * 2);
        float2 f = __half22float2(h);
        acc = f.x * x[lane * 2] + f.y * x[lane * 2 + 1];
    }
    return acc;
}

__device__ __forceinline__ float sigm(float x) { return 1.f / (1.f + __expf(-x)); }

// ---- split grid barrier: arrive (release) / wait (per-slot acquire poll) ------
__device__ __forceinline__ void bar_arrive(unsigned ep) {
    __syncthreads();
    if (threadIdx.x == 0)
        asm volatile("st.release.gpu.global.b32 [%0], %1;"
                     :: "l"(g_arrive + blockIdx.x), "r"(ep) : "memory");
}
__device__ __forceinline__ void bar_wait(unsigned ep) {
    if (threadIdx.x < NBLK) {
        const unsigned* p = g_arrive + threadIdx.x;
        unsigned v;
        do {
            asm volatile("ld.acquire.gpu.global.b32 %0, [%1];"
                         : "=r"(v) : "l"(p) : "memory");
        } while ((int)(v - ep) < 0);
    }
    __syncthreads();
}

__device__ __forceinline__ float block_sum(float v, float* sred) {
    int lane = threadIdx.x & 31, w = threadIdx.x >> 5;
    v = warp_red(v);
    if (lane == 0) sred[w] = v;
    __syncthreads();
    float r = 0.f;
    if (w == 0) {
        r = (lane < NTHR / 32) ? sred[lane] : 0.f;
        r = warp_red(r);
    }
    __syncthreads();
    return r;
}

// Standard bg (blocks 1..147): tasks = 4096 G rows + nv V rows, loop over bgw.
__device__ __forceinline__ void bg_work(int bgw, int lane,
                                        const unsigned char* __restrict__ gwts,
                                        const __half* __restrict__ gin,
                                        float* __restrict__ gout,
                                        const float* __restrict__ gbase,
                                        int nv,
                                        const __half* __restrict__ vwts,
                                        const __half* __restrict__ vin,
                                        __half* __restrict__ vout,
                                        const float* __restrict__ vbias) {
    const int total = 4096 + nv;
    for (int task = bgw; task < total; task += NBGW) {
        if (task < 4096) {
            float a = warp_red(dot8<2048>(gwts + (size_t)task * 2048, gin, lane));
            if (lane == 0) stf(&gout[task], a * INV_WSCALE + gbase[task]);
        } else {
            int v = task - 4096;
            float a = warp_red(dot16<2048>(vwts + (size_t)v * 1024, vin, lane));
            if (lane == 0) sth(&vout[v], a + vbias[v]);
        }
    }
}

// Heavy P0 bg (blocks 1..147): Gtop(h5) + G3(prv) + reconR[3](h5) + reconR[2](h3).
__device__ __forceinline__ void bg_p0(int bgw, int lane, int t,
                                      const __half* __restrict__ sh5,
                                      const __half* __restrict__ prv,
                                      const float* __restrict__ Vmid_b) {
    const int vmax = (t > 0) ? 10240 : 8192;   // skip recon writes at t=0 (zero carry)
    for (int task = bgw; task < vmax; task += NBGW) {
        if (task < 4096) {
            float a = warp_red(dot8<1024>(w8_Gtop + (size_t)task * 1024, sh5, lane));
            if (lane == 0) stf(&g_G[4][task], a * INV_WSCALE + d_gbase[4][task]);
        } else if (task < 8192) {
            int r = task - 4096;
            float a = warp_red(dot8<2048>(&w8_G[3][(size_t)r * 2048], prv, lane));
            if (lane == 0) stf(&g_G[3][r], a * INV_WSCALE + d_gbase[3][r]);
        } else if (task < 9216) {
            int v = task - 8192;
            float a = warp_red(dot16<2048>(h_Vmid + (size_t)3 * 1048576 + (size_t)v * 1024, sh5, lane));
            if (lane == 0) sth(&g_reconR[3][v], a + Vmid_b[3072 + v]);
        } else {
            int v = task - 9216;
            float a = warp_red(dot16<2048>(h_Vmid + (size_t)2 * 1048576 + (size_t)v * 1024, prv + 1024, lane));
            if (lane == 0) sth(&g_reconR[2][v], a + Vmid_b[2048 + v]);
        }
    }
}

// ---------------- launch #1: fp16 staging for the fold GEMM ---------------------
__global__ void conv_ab(const float* __restrict__ Wihm, const float* __restrict__ Wiht,
                        const float* __restrict__ Wmid) {
    long i0 = (long)blockIdx.x * blockDim.x + threadIdx.x;
    long st = (long)gridDim.x * blockDim.x;
    for (long i = i0; i < 4L * 4096 * 256; i += st) {
        long zr = i >> 8;
        int z = (int)(zr >> 12);
        long r = zr & 4095;
        int cc = (int)(i & 255) * 4;
        const float* src = (z < 3) ? (Wihm + ((size_t)(z + 1) * 4096 + r) * 2048 + cc)
                                   : (Wiht + (size_t)r * 1024 + cc);
        float4 v = *reinterpret_cast<const float4*>(src);
        *reinterpret_cast<__half2*>(h_A16 + zr * 1024 + cc)     = __floats2half2_rn(v.x, v.y);
        *reinterpret_cast<__half2*>(h_A16 + zr * 1024 + cc + 2) = __floats2half2_rn(v.z, v.w);
    }
    for (long i = i0; i < 4L * 1024 * 1024; i += st) {
        long z = i >> 20;
        int ii = (int)((i >> 10) & 1023);
        int j  = (int)(i & 1023);
        h_BT[z * 1048576 + (size_t)j * 1024 + ii] =
            __float2half_rn(Wmid[z * 1048576 + (size_t)ii * 1024 + j]);
    }
}

// ---------------- launch #2: gbase + F0-fold + quantize/pack (merged) -----------
__global__ void prep_merged(const float* __restrict__ Wihm, const float* __restrict__ Wiht,
                            const float* __restrict__ W0_b, const float* __restrict__ Wmid_b,
                            const float* __restrict__ bmid, const float* __restrict__ btop,
                            const float* __restrict__ V1, const float* __restrict__ Vmid,
                            const float* __restrict__ Whhm, const float* __restrict__ Whht,
                            const float* __restrict__ W0w) {
    int gwarp = (blockIdx.x * blockDim.x + threadIdx.x) >> 5;
    int lane = threadIdx.x & 31;
    if (gwarp < 5 * 4096) {
        // part 1: gbase (warp per row)
        int lay = gwarp >> 12;
        int r = gwarp & 4095;
        const float* Arow;
        const float* bv;
        float bias;
        if (lay < 4) {
            Arow = Wihm + ((size_t)lay * 4096 + r) * 2048;
            bv = (lay == 0) ? W0_b : (Wmid_b + (lay - 1) * 1024);
            bias = bmid[lay * 4096 + r];
        } else {
            Arow = Wiht + (size_t)r * 1024;
            bv = Wmid_b + 3 * 1024;
            bias = btop[r];
        }
        float s = 0.f;
        for (int j = lane; j < 1024; j += 32) s = fmaf(Arow[j], bv[j], s);
        s = warp_red(s);
        if (lane == 0) d_gbase[lay][r] = s + bias;
    } else if (gwarp < 6 * 4096) {
        // part 2: F0 = Wih0[:,:H] x W0 (warp per row)
        int r = gwarp - 5 * 4096;
        float a[32];
        const float* Arow = Wihm + (size_t)r * 2048;
#pragma unroll
        for (int j = 0; j < 32; j++) a[j] = Arow[lane + 32 * j];
        for (int c = 0; c < CC; c++) {
            float s = 0.f;
#pragma unroll
            for (int j = 0; j < 32; j++) s = fmaf(a[j], W0w[(lane + 32 * j) * CC + c], s);
            s = warp_red(s);
            if (lane == 0) h_F0[(size_t)r * 64 + c] = __float2half_rn(s);
        }
    }
    // part 3: quantize/pack (grid-stride)
    long i0 = (long)blockIdx.x * blockDim.x + threadIdx.x;
    long st = (long)gridDim.x * blockDim.x;
#define PACK8(v) ( (unsigned)__nv_cvt_float2_to_fp8x2(make_float2((v).x*64.f,(v).y*64.f), __NV_SATFINITE, __NV_E4M3) \
                 | ((unsigned)__nv_cvt_float2_to_fp8x2(make_float2((v).z*64.f,(v).w*64.f), __NV_SATFINITE, __NV_E4M3) << 16) )
    for (long i = i0; i < 16384L * 256; i += st) {
        long row = i >> 8; int jj = (int)(i & 255) * 4;
        float4 v = *reinterpret_cast<const float4*>(Wihm + row * 2048 + 1024 + jj);
        reinterpret_cast<unsigned*>(&w8_G[0][0])[row * 512 + (jj >> 2)] = PACK8(v);
    }
    for (long i = i0; i < 16384L * 256; i += st) {
        long row = i >> 8; int jj = (int)(i & 255) * 4;
        float4 v = *reinterpret_cast<const float4*>(Whhm + row * 1024 + jj);
        reinterpret_cast<unsigned*>(&w8_G[0][0])[row * 512 + 256 + (jj >> 2)] = PACK8(v);
    }
    for (long i = i0; i < 4096L * 256; i += st) {
        float4 v = *reinterpret_cast<const float4*>(Whht + i * 4);
        reinterpret_cast<unsigned*>(w8_Gtop)[i] = PACK8(v);
    }
#undef PACK8
    for (long i = i0; i < 4L * 1024 * 1024 / 2; i += st)
        reinterpret_cast<__half2*>(h_Vmid)[i] = __float22half2_rn(reinterpret_cast<const float2*>(Vmid)[i]);
    for (long i = i0; i < 56L * 1024 / 2; i += st)
        reinterpret_cast<__half2*>(h_V1)[i] = __float22half2_rn(reinterpret_cast<const float2*>(V1)[i]);
}

// ---------------- launch #3: fold GEMM via mma.sync (HMMA, fp16 out) ------------
__global__ void gemm_fold_mma() {
    const int z = blockIdx.z;
    const __half* A  = h_A16 + (size_t)z * 4096 * 1024;
    const __half* BT = h_BT  + (size_t)z * 1024 * 1024;
    __half* C = &h_F[z][0];
    const int wid = threadIdx.x >> 5, lane = threadIdx.x & 31;
    const int wm = wid >> 1, wn = wid & 1;
    const int m0 = blockIdx.y * 128 + wm * 32;
    const int n0 = blockIdx.x * 64 + wn * 32;
    const int ra = lane >> 2, kc = (lane & 3) * 2;
    float d[2][4][4] = {};
    for (int k0 = 0; k0 < 1024; k0 += 16) {
        unsigned a[2][4], b[4][2];
#pragma unroll
        for (int t = 0; t < 2; t++) {
            const __half* Ab = A + (size_t)(m0 + t * 16 + ra) * 1024 + k0 + kc;
            a[t][0] = *reinterpret_cast<const unsigned*>(Ab);
            a[t][1] = *reinterpret_cast<const unsigned*>(Ab + 8 * 1024);
            a[t][2] = *reinterpret_cast<const unsigned*>(Ab + 8);
            a[t][3] = *reinterpret_cast<const unsigned*>(Ab + 8 * 1024 + 8);
        }
#pragma unroll
        for (int u = 0; u < 4; u++) {
            const __half* Bb = BT + (size_t)(n0 + u * 8 + ra) * 1024 + k0 + kc;
            b[u][0] = *reinterpret_cast<const unsigned*>(Bb);
            b[u][1] = *reinterpret_cast<const unsigned*>(Bb + 8);
        }
#pragma unroll
        for (int t = 0; t < 2; t++)
#pragma unroll
            for (int u = 0; u < 4; u++)
                asm volatile(
                    "mma.sync.aligned.m16n8k16.row.col.f32.f16.f16.f32 "
                    "{%0,%1,%2,%3}, {%4,%5,%6,%7}, {%8,%9}, {%0,%1,%2,%3};"
                    : "+f"(d[t][u][0]), "+f"(d[t][u][1]), "+f"(d[t][u][2]), "+f"(d[t][u][3])
                    : "r"(a[t][0]), "r"(a[t][1]), "r"(a[t][2]), "r"(a[t][3]),
                      "r"(b[u][0]), "r"(b[u][1]));
    }
#pragma unroll
    for (int t = 0; t < 2; t++)
#pragma unroll
        for (int u = 0; u < 4; u++) {
            int r = m0 + t * 16 + ra, c = n0 + u * 8 + kc;
            *reinterpret_cast<__half2*>(C + (size_t)r * 1024 + c) =
                __floats2half2_rn(d[t][u][0], d[t][u][1]);
            *reinterpret_cast<__half2*>(C + (size_t)(r + 8) * 1024 + c) =
                __floats2half2_rn(d[t][u][2], d[t][u][3]);
        }
}

// ---------------- launch #4: main persistent kernel -----------------------------
__global__ void __launch_bounds__(NTHR, 1)
predcells_kernel(const float* __restrict__ x_seq,
                 const float* __restrict__ V1_b, const float* __restrict__ Vmid_b,
                 float* __restrict__ out) {
    __shared__ __align__(16) __half sbufA[2][2048];   // ping-pong [TD|h]
    __shared__ __align__(16) __half sh5[HH];          // top hidden (t-1), same-phase use
    __shared__ float sTD0[64];
    __shared__ float sred[32];

    const int tid  = threadIdx.x;
    const int lane = tid & 31;
    const int wid  = tid >> 5;
    const int gw   = blockIdx.x * (NTHR / 32) + wid;
    const int bgw  = gw - 32;                          // bg warp index (blocks 1..147)
    const long gtid = (long)blockIdx.x * NTHR + tid;
    const long gsz  = (long)NBLK * NTHR;

    float c_reg[5] = {0.f, 0.f, 0.f, 0.f, 0.f};
    unsigned ep = g_arrive[blockIdx.x];

    // ---- prologue A: init state ----
    for (int i = tid; i < 4096; i += NTHR) (&sbufA[0][0])[i] = __ushort_as_half(0);
    for (long i = gtid; i < 4 * HH; i += gsz) (&g_reconR[0][0])[i] = __ushort_as_half(0);
    for (long i = gtid; i < 64; i += gsz) g_recon1[i] = __ushort_as_half(0);
    for (long i = gtid; i < 5 * 4096; i += gsz) (&g_G[0][0])[i] = (&d_gbase[0][0])[i];
    float td0p = 0.f;
    if (tid < CC) { td0p = fabsf(x_seq[tid]); sTD0[tid] = td0p; }
    bar_arrive(++ep);
    bar_wait(ep);

    // ---- prologue B: z_0(0) = F0*|x_0| + G_0 ----
    if (gw < 4096) {
        float a = warp_red(dot56h(&h_F0[(size_t)gw * 64], sTD0, lane));
        if (lane == 0) stf(&g_z[0][gw], a + ldf(&g_G[0][gw]));
    }
    bar_arrive(++ep);
    if (blockIdx.x == 0) {
        float s = block_sum(td0p, sred);
        if (tid == 0) stf(&g_loss_parts[0][0], s);
    }
    bar_wait(ep);

    int pp = 0;
    for (int t = 0; t < TT; t++) {
        // ================= phase 0: gates L0(t) + gates L4(t-1) ==================
        {
            __half* cur = &sbufA[pp][0];
            const __half* prv = &sbufA[pp ^ 1][0];   // [TD3(t-1) | h3(t-1)]
            float td;
            {
                const int k = tid;
                float zi = ldf(&g_z[0][k]);
                float zf = ldf(&g_z[0][1024 + k]);
                float zg = ldf(&g_z[0][2048 + k]);
                float zo = ldf(&g_z[0][3072 + k]);
                float cn = sigm(zf) * c_reg[0] + sigm(zi) * tanhf(zg);
                c_reg[0] = cn;
                float hn = sigm(zo) * tanhf(cn);
                td = fabsf(hn - ldh(&g_reconR[0][k]));
                cur[k] = __float2half_rn(td);
                cur[1024 + k] = __float2half_rn(hn);
                if (t > 0) {   // top-layer gates for step t-1
                    float ti = ldf(&g_z[4][k]);
                    float tf = ldf(&g_z[4][1024 + k]);
                    float tg = ldf(&g_z[4][2048 + k]);
                    float to = ldf(&g_z[4][3072 + k]);
                    float tc = sigm(tf) * c_reg[4] + sigm(ti) * tanhf(tg);
                    c_reg[4] = tc;
                    sh5[k] = __float2half_rn(sigm(to) * tanhf(tc));
                } else {
                    sh5[k] = __ushort_as_half(0);
                }
            }
            __syncthreads();
            if (gw < 4096) {     // chain: z1 = F[0]*TD0 + G1
                float a = warp_red(dot16<2048>(&h_F[0][(size_t)gw * 1024], cur, lane));
                if (lane == 0) stf(&g_z[1][gw], a + ldf(&g_G[1][gw]));
            }
            bar_arrive(++ep);
            if (blockIdx.x > 0) {
                bg_p0(bgw, lane, t, sh5, prv, Vmid_b);
            } else {
                float s = block_sum(td, sred);
                if (tid == 0) stf(&g_loss_parts[t][1], s);
            }
            bar_wait(ep);
            pp ^= 1;
        }

        // ================= phases 1..2: mid layers ===============================
#pragma unroll 1
        for (int ph = 1; ph <= 2; ph++) {
            __half* cur = &sbufA[pp][0];
            const __half* prv = &sbufA[pp ^ 1][0];
            float td;
            {
                const int k = tid;
                float zi = ldf(&g_z[ph][k]);
                float zf = ldf(&g_z[ph][1024 + k]);
                float zg = ldf(&g_z[ph][2048 + k]);
                float zo = ldf(&g_z[ph][3072 + k]);
                float cn = sigm(zf) * c_reg[ph] + sigm(zi) * tanhf(zg);
                c_reg[ph] = cn;
                float hn = sigm(zo) * tanhf(cn);
                td = fabsf(hn - ldh(&g_reconR[ph][k]));
                cur[k] = __float2half_rn(td);
                cur[1024 + k] = __float2half_rn(hn);
            }
            __syncthreads();
            if (gw < 4096) {
                float a = warp_red(dot16<2048>(&h_F[ph][(size_t)gw * 1024], cur, lane));
                if (lane == 0) stf(&g_z[ph + 1][gw], a + ldf(&g_G[ph + 1][gw]));
            }
            bar_arrive(++ep);
            if (blockIdx.x > 0) {
                if (ph == 1)
                    bg_work(bgw, lane, &w8_G[0][0], prv, g_G[0], d_gbase[0],
                            56, h_V1, prv + 1024, g_recon1, V1_b);
                else
                    bg_work(bgw, lane, &w8_G[1][0], prv, g_G[1], d_gbase[1],
                            1024, h_Vmid, prv + 1024, g_reconR[0], Vmid_b);
            } else {
                float s = block_sum(td, sred);
                if (tid == 0) stf(&g_loss_parts[t][1 + ph], s);
            }
            bar_wait(ep);
            pp ^= 1;
        }

        // ================= phase 3: gates L3 + dual chain (z4, z0(t+1)) ==========
        {
            const bool more = (t + 1 < TT);
            __half* cur = &sbufA[pp][0];
            const __half* prv = &sbufA[pp ^ 1][0];   // [TD2 | h2]
            float td;
            {
                const int k = tid;
                float zi = ldf(&g_z[3][k]);
                float zf = ldf(&g_z[3][1024 + k]);
                float zg = ldf(&g_z[3][2048 + k]);
                float zo = ldf(&g_z[3][3072 + k]);
                float cn = sigm(zf) * c_reg[3] + sigm(zi) * tanhf(zg);
                c_reg[3] = cn;
                float hn = sigm(zo) * tanhf(cn);
                td = fabsf(hn - ldh(&g_reconR[3][k]));
                cur[k] = __float2half_rn(td);
                cur[1024 + k] = __float2half_rn(hn);
            }
            float td0 = 0.f;
            if (more && tid < CC) {
                td0 = fabsf(x_seq[(t + 1) * CC + tid] - ldh(&g_recon1[tid]));
                sTD0[tid] = td0;
            }
            __syncthreads();
            if (gw < 4096) {
                float a = warp_red(dot16<2048>(&h_F[3][(size_t)gw * 1024], cur, lane));
                if (lane == 0) stf(&g_z[4][gw], a + ldf(&g_G[4][gw]));
                if (more) {
                    float b = warp_red(dot56h(&h_F0[(size_t)gw * 64], sTD0, lane));
                    if (lane == 0) stf(&g_z[0][gw], b + ldf(&g_G[0][gw]));
                }
            }
            bar_arrive(++ep);
            if (blockIdx.x > 0) {
                bg_work(bgw, lane, &w8_G[2][0], prv, g_G[2], d_gbase[2],
                        1024, h_Vmid + (size_t)1048576, prv + 1024, g_reconR[1], Vmid_b + 1024);
            } else {
                float s = block_sum(td, sred);
                if (tid == 0) stf(&g_loss_parts[t][4], s);
                float s0 = block_sum(td0, sred);
                if (more && tid == 0) stf(&g_loss_parts[t + 1][0], s0);
            }
            bar_wait(ep);
            pp ^= 1;
        }
    }

    // ---- epilogue: deterministic loss reduction ----
    if (blockIdx.x == 0) {
        const float* parts = &g_loss_parts[0][0];
        float v = 0.f;
        for (int i = tid; i < TT * 5; i += NTHR) v += ldf(&parts[i]);
        float s = block_sum(v, sred);
        if (tid == 0) out[0] = s;
    }
}

// ---------------- launch (exactly 4 kernels: predcells is global launch #4) ------
extern "C" void kernel_launch(void* const* d_in, const int* in_sizes, int n_in,
                              void* d_out, int out_size) {
    (void)in_sizes; (void)n_in; (void)out_size;
    const float* x_seq  = (const float*)d_in[0];
    const float* W0_w   = (const float*)d_in[1];
    const float* W0_b   = (const float*)d_in[2];
    const float* Wmid_w = (const float*)d_in[3];
    const float* Wmid_b = (const float*)d_in[4];
    const float* V1_w   = (const float*)d_in[5];
    const float* V1_b   = (const float*)d_in[6];
    const float* Vmid_w = (const float*)d_in[7];
    const float* Vmid_b = (const float*)d_in[8];
    const float* Wihm   = (const float*)d_in[9];
    const float* Whhm   = (const float*)d_in[10];
    const float* bmid   = (const float*)d_in[11];
    const float* Wiht   = (const float*)d_in[12];
    const float* Whht   = (const float*)d_in[13];
    const float* btop   = (const float*)d_in[14];

    conv_ab<<<2048, 256>>>(Wihm, Wiht, Wmid_w);
    prep_merged<<<3072, 256>>>(Wihm, Wiht, W0_b, Wmid_b, bmid, btop,
                               V1_w, Vmid_w, Whhm, Whht, W0_w);
    gemm_fold_mma<<<dim3(16, 32, 4), 256>>>();
    predcells_kernel<<<NBLK, NTHR>>>(x_seq, V1_b, Vmid_b, (float*)d_out);
}

// round 15
// speedup vs baseline: 1.0070x; 1.0070x over previous
#include <cuda_runtime.h>
#include <cuda_fp16.h>
#include <cuda_fp8.h>

#define TT 256
#define CC 56
#define HH 1024
#define NBLK 148
#define NTHR 1024
#define NBGW 4704                /* bg warps: blocks 1..147 x 32 */
#define INV_WSCALE (1.0f/64.0f)
#define FLAGSTRIDE 32            /* one flag per 128B L2 line */

// ---------------- folded / quantized weights (built per launch) ----------------
__device__ __align__(16) __half  h_F[4][(size_t)4096*1024];   // F_{m->m+1} fp16
__device__ __align__(16) __half  h_F0[(size_t)4096*64];       // Wih0[:,:H]*W0
__device__ __align__(16) unsigned char w8_G[4][(size_t)4096*2048]; // [Wih[:,H:]|Whh] fp8
__device__ __align__(16) unsigned char w8_Gtop[(size_t)4096*1024]; // Whh_top fp8
__device__ __align__(16) __half  h_Vmid[(size_t)4*1024*1024];
__device__ __align__(16) __half  h_V1[(size_t)56*1024];
__device__ float d_gbase[5][4096];

// fp16 staging for the tensor-core fold GEMM
__device__ __align__(16) __half  h_A16[(size_t)4*4096*1024];
__device__ __align__(16) __half  h_BT[(size_t)4*1024*1024];

// ---------------- runtime state ------------------------------------------------
__device__ float g_z[5][4096];
__device__ float g_G[5][4096];
__device__ __align__(4) __half g_reconR[4][HH];
__device__ __align__(4) __half g_recon1[64];
__device__ float g_loss_parts[TT][5];
__device__ __align__(128) unsigned g_arrive[NBLK * FLAGSTRIDE];  // padded: 1 flag / 128B line

// ---------------- helpers ------------------------------------------------------
__device__ __forceinline__ float ldf(const float* p) { return __ldcg(p); }
__device__ __forceinline__ void  stf(float* p, float v) { __stcg(p, v); }
__device__ __forceinline__ float ldh(const __half* p) {
    unsigned short u = __ldcg(reinterpret_cast<const unsigned short*>(p));
    return __half2float(__ushort_as_half(u));
}
__device__ __forceinline__ void sth(__half* p, float v) {
    __stcg(reinterpret_cast<unsigned short*>(p), __half_as_ushort(__float2half_rn(v)));
}

__device__ __forceinline__ float warp_red(float v) {
#pragma unroll
    for (int o = 16; o; o >>= 1) v += __shfl_xor_sync(0xffffffffu, v, o);
    return v;
}

__device__ __forceinline__ __half2 cvt8(unsigned v16) {
    __half2_raw r = __nv_cvt_fp8x2_to_halfraw2((__nv_fp8x2_storage_t)v16, __NV_E4M3);
    return *reinterpret_cast<__half2*>(&r);
}
__device__ __forceinline__ float hsum(__half2 h) {
    float2 f = __half22float2(h);
    return f.x + f.y;
}

template<int NB>
__device__ __forceinline__ float dot8(const unsigned char* __restrict__ w,
                                      const __half* __restrict__ x, int lane) {
    float acc = 0.f;
#pragma unroll
    for (int it = 0; it < NB / 512; it++) {
        int c = it * 512 + lane * 16;
        uint4 wv  = *reinterpret_cast<const uint4*>(w + c);
        uint4 xv0 = *reinterpret_cast<const uint4*>(reinterpret_cast<const char*>(x) + 2 * c);
        uint4 xv1 = *reinterpret_cast<const uint4*>(reinterpret_cast<const char*>(x) + 2 * c + 16);
        const __half2* xa = reinterpret_cast<const __half2*>(&xv0);
        const __half2* xb = reinterpret_cast<const __half2*>(&xv1);
        __half2 s = __floats2half2_rn(0.f, 0.f);
        s = __hfma2(cvt8(wv.x & 0xffffu), xa[0], s);
        s = __hfma2(cvt8(wv.x >> 16),     xa[1], s);
        s = __hfma2(cvt8(wv.y & 0xffffu), xa[2], s);
        s = __hfma2(cvt8(wv.y >> 16),     xa[3], s);
        s = __hfma2(cvt8(wv.z & 0xffffu), xb[0], s);
        s = __hfma2(cvt8(wv.z >> 16),     xb[1], s);
        s = __hfma2(cvt8(wv.w & 0xffffu), xb[2], s);
        s = __hfma2(cvt8(wv.w >> 16),     xb[3], s);
        acc += hsum(s);
    }
    return acc;
}

template<int NB>
__device__ __forceinline__ float dot16(const __half* __restrict__ w,
                                       const __half* __restrict__ x, int lane) {
    float acc = 0.f;
#pragma unroll
    for (int it = 0; it < NB / 512; it++) {
        int c = it * 512 + lane * 16;
        uint4 wv = *reinterpret_cast<const uint4*>(reinterpret_cast<const char*>(w) + c);
        uint4 xv = *reinterpret_cast<const uint4*>(reinterpret_cast<const char*>(x) + c);
        const __half2* wa = reinterpret_cast<const __half2*>(&wv);
        const __half2* xa = reinterpret_cast<const __half2*>(&xv);
        __half2 s = __floats2half2_rn(0.f, 0.f);
        s = __hfma2(wa[0], xa[0], s);
        s = __hfma2(wa[1], xa[1], s);
        s = __hfma2(wa[2], xa[2], s);
        s = __hfma2(wa[3], xa[3], s);
        acc += hsum(s);
    }
    return acc;
}

__device__ __forceinline__ float dot56h(const __half* __restrict__ w,
                                        const float* __restrict__ x, int lane) {
    float acc = 0.f;
    if (lane < 28) {
        __half2 h = *reinterpret_cast<const __half2*>(w + lane * 2);
        float2 f = __half22float2(h);
        acc = f.x * x[lane * 2] + f.y * x[lane * 2 + 1];
    }
    return acc;
}

__device__ __forceinline__ float sigm(float x) { return 1.f / (1.f + __expf(-x)); }

// ---- split grid barrier: arrive (release) / wait (warp-scan over padded flags) -
__device__ __forceinline__ void bar_arrive(unsigned ep) {
    __syncthreads();
    if (threadIdx.x == 0)
        asm volatile("st.release.gpu.global.b32 [%0], %1;"
                     :: "l"(g_arrive + blockIdx.x * FLAGSTRIDE), "r"(ep) : "memory");
}
__device__ __forceinline__ void bar_wait(unsigned ep) {
    if (threadIdx.x < 32) {
        const int lane = threadIdx.x;
        bool done = false;
        while (!done) {
            bool ok = true;
#pragma unroll
            for (int j = 0; j < 5; j++) {
                int s = lane + j * 32;
                if (s < NBLK) {
                    unsigned v;
                    asm volatile("ld.acquire.gpu.global.b32 %0, [%1];"
                                 : "=r"(v) : "l"(g_arrive + s * FLAGSTRIDE) : "memory");
                    ok &= ((int)(v - ep) >= 0);
                }
            }
            done = __all_sync(0xffffffffu, ok);
        }
    }
    __syncthreads();
}

__device__ __forceinline__ float block_sum(float v, float* sred) {
    int lane = threadIdx.x & 31, w = threadIdx.x >> 5;
    v = warp_red(v);
    if (lane == 0) sred[w] = v;
    __syncthreads();
    float r = 0.f;
    if (w == 0) {
        r = (lane < NTHR / 32) ? sred[lane] : 0.f;
        r = warp_red(r);
    }
    __syncthreads();
    return r;
}

// Standard bg (blocks 1..147): tasks = 4096 G rows + nv V rows, loop over bgw.
__device__ __forceinline__ void bg_work(int bgw, int lane,
                                        const unsigned char* __restrict__ gwts,
                                        const __half* __restrict__ gin,
                                        float* __restrict__ gout,
                                        const float* __restrict__ gbase,
                                        int nv,
                                        const __half* __restrict__ vwts,
                                        const __half* __restrict__ vin,
                                        __half* __restrict__ vout,
                                        const float* __restrict__ vbias) {
    const int total = 4096 + nv;
    for (int task = bgw; task < total; task += NBGW) {
        if (task < 4096) {
            float a = warp_red(dot8<2048>(gwts + (size_t)task * 2048, gin, lane));
            if (lane == 0) stf(&gout[task], a * INV_WSCALE + gbase[task]);
        } else {
            int v = task - 4096;
            float a = warp_red(dot16<2048>(vwts + (size_t)v * 1024, vin, lane));
            if (lane == 0) sth(&vout[v], a + vbias[v]);
        }
    }
}

// Heavy P0 bg (blocks 1..147): Gtop(h5) + G3(prv) + reconR[3](h5) + reconR[2](h3).
__device__ __forceinline__ void bg_p0(int bgw, int lane, int t,
                                      const __half* __restrict__ sh5,
                                      const __half* __restrict__ prv,
                                      const float* __restrict__ Vmid_b) {
    const int vmax = (t > 0) ? 10240 : 8192;   // skip recon writes at t=0 (zero carry)
    for (int task = bgw; task < vmax; task += NBGW) {
        if (task < 4096) {
            float a = warp_red(dot8<1024>(w8_Gtop + (size_t)task * 1024, sh5, lane));
            if (lane == 0) stf(&g_G[4][task], a * INV_WSCALE + d_gbase[4][task]);
        } else if (task < 8192) {
            int r = task - 4096;
            float a = warp_red(dot8<2048>(&w8_G[3][(size_t)r * 2048], prv, lane));
            if (lane == 0) stf(&g_G[3][r], a * INV_WSCALE + d_gbase[3][r]);
        } else if (task < 9216) {
            int v = task - 8192;
            float a = warp_red(dot16<2048>(h_Vmid + (size_t)3 * 1048576 + (size_t)v * 1024, sh5, lane));
            if (lane == 0) sth(&g_reconR[3][v], a + Vmid_b[3072 + v]);
        } else {
            int v = task - 9216;
            float a = warp_red(dot16<2048>(h_Vmid + (size_t)2 * 1048576 + (size_t)v * 1024, prv + 1024, lane));
            if (lane == 0) sth(&g_reconR[2][v], a + Vmid_b[2048 + v]);
        }
    }
}

// ---------------- launch #1: fp16 staging for the fold GEMM ---------------------
__global__ void conv_ab(const float* __restrict__ Wihm, const float* __restrict__ Wiht,
                        const float* __restrict__ Wmid) {
    long i0 = (long)blockIdx.x * blockDim.x + threadIdx.x;
    long st = (long)gridDim.x * blockDim.x;
    for (long i = i0; i < 4L * 4096 * 256; i += st) {
        long zr = i >> 8;
        int z = (int)(zr >> 12);
        long r = zr & 4095;
        int cc = (int)(i & 255) * 4;
        const float* src = (z < 3) ? (Wihm + ((size_t)(z + 1) * 4096 + r) * 2048 + cc)
                                   : (Wiht + (size_t)r * 1024 + cc);
        float4 v = *reinterpret_cast<const float4*>(src);
        *reinterpret_cast<__half2*>(h_A16 + zr * 1024 + cc)     = __floats2half2_rn(v.x, v.y);
        *reinterpret_cast<__half2*>(h_A16 + zr * 1024 + cc + 2) = __floats2half2_rn(v.z, v.w);
    }
    for (long i = i0; i < 4L * 1024 * 1024; i += st) {
        long z = i >> 20;
        int ii = (int)((i >> 10) & 1023);
        int j  = (int)(i & 1023);
        h_BT[z * 1048576 + (size_t)j * 1024 + ii] =
            __float2half_rn(Wmid[z * 1048576 + (size_t)ii * 1024 + j]);
    }
}

// ---------------- launch #2: gbase + F0-fold + quantize/pack (merged) -----------
__global__ void prep_merged(const float* __restrict__ Wihm, const float* __restrict__ Wiht,
                            const float* __restrict__ W0_b, const float* __restrict__ Wmid_b,
                            const float* __restrict__ bmid, const float* __restrict__ btop,
                            const float* __restrict__ V1, const float* __restrict__ Vmid,
                            const float* __restrict__ Whhm, const float* __restrict__ Whht,
                            const float* __restrict__ W0w) {
    int gwarp = (blockIdx.x * blockDim.x + threadIdx.x) >> 5;
    int lane = threadIdx.x & 31;
    if (gwarp < 5 * 4096) {
        int lay = gwarp >> 12;
        int r = gwarp & 4095;
        const float* Arow;
        const float* bv;
        float bias;
        if (lay < 4) {
            Arow = Wihm + ((size_t)lay * 4096 + r) * 2048;
            bv = (lay == 0) ? W0_b : (Wmid_b + (lay - 1) * 1024);
            bias = bmid[lay * 4096 + r];
        } else {
            Arow = Wiht + (size_t)r * 1024;
            bv = Wmid_b + 3 * 1024;
            bias = btop[r];
        }
        float s = 0.f;
        for (int j = lane; j < 1024; j += 32) s = fmaf(Arow[j], bv[j], s);
        s = warp_red(s);
        if (lane == 0) d_gbase[lay][r] = s + bias;
    } else if (gwarp < 6 * 4096) {
        int r = gwarp - 5 * 4096;
        float a[32];
        const float* Arow = Wihm + (size_t)r * 2048;
#pragma unroll
        for (int j = 0; j < 32; j++) a[j] = Arow[lane + 32 * j];
        for (int c = 0; c < CC; c++) {
            float s = 0.f;
#pragma unroll
            for (int j = 0; j < 32; j++) s = fmaf(a[j], W0w[(lane + 32 * j) * CC + c], s);
            s = warp_red(s);
            if (lane == 0) h_F0[(size_t)r * 64 + c] = __float2half_rn(s);
        }
    }
    long i0 = (long)blockIdx.x * blockDim.x + threadIdx.x;
    long st = (long)gridDim.x * blockDim.x;
#define PACK8(v) ( (unsigned)__nv_cvt_float2_to_fp8x2(make_float2((v).x*64.f,(v).y*64.f), __NV_SATFINITE, __NV_E4M3) \
                 | ((unsigned)__nv_cvt_float2_to_fp8x2(make_float2((v).z*64.f,(v).w*64.f), __NV_SATFINITE, __NV_E4M3) << 16) )
    for (long i = i0; i < 16384L * 256; i += st) {
        long row = i >> 8; int jj = (int)(i & 255) * 4;
        float4 v = *reinterpret_cast<const float4*>(Wihm + row * 2048 + 1024 + jj);
        reinterpret_cast<unsigned*>(&w8_G[0][0])[row * 512 + (jj >> 2)] = PACK8(v);
    }
    for (long i = i0; i < 16384L * 256; i += st) {
        long row = i >> 8; int jj = (int)(i & 255) * 4;
        float4 v = *reinterpret_cast<const float4*>(Whhm + row * 1024 + jj);
        reinterpret_cast<unsigned*>(&w8_G[0][0])[row * 512 + 256 + (jj >> 2)] = PACK8(v);
    }
    for (long i = i0; i < 4096L * 256; i += st) {
        float4 v = *reinterpret_cast<const float4*>(Whht + i * 4);
        reinterpret_cast<unsigned*>(w8_Gtop)[i] = PACK8(v);
    }
#undef PACK8
    for (long i = i0; i < 4L * 1024 * 1024 / 2; i += st)
        reinterpret_cast<__half2*>(h_Vmid)[i] = __float22half2_rn(reinterpret_cast<const float2*>(Vmid)[i]);
    for (long i = i0; i < 56L * 1024 / 2; i += st)
        reinterpret_cast<__half2*>(h_V1)[i] = __float22half2_rn(reinterpret_cast<const float2*>(V1)[i]);
}

// ---------------- launch #3: fold GEMM via mma.sync (HMMA, fp16 out) ------------
__global__ void gemm_fold_mma() {
    const int z = blockIdx.z;
    const __half* A  = h_A16 + (size_t)z * 4096 * 1024;
    const __half* BT = h_BT  + (size_t)z * 1024 * 1024;
    __half* C = &h_F[z][0];
    const int wid = threadIdx.x >> 5, lane = threadIdx.x & 31;
    const int wm = wid >> 1, wn = wid & 1;
    const int m0 = blockIdx.y * 128 + wm * 32;
    const int n0 = blockIdx.x * 64 + wn * 32;
    const int ra = lane >> 2, kc = (lane & 3) * 2;
    float d[2][4][4] = {};
    for (int k0 = 0; k0 < 1024; k0 += 16) {
        unsigned a[2][4], b[4][2];
#pragma unroll
        for (int t = 0; t < 2; t++) {
            const __half* Ab = A + (size_t)(m0 + t * 16 + ra) * 1024 + k0 + kc;
            a[t][0] = *reinterpret_cast<const unsigned*>(Ab);
            a[t][1] = *reinterpret_cast<const unsigned*>(Ab + 8 * 1024);
            a[t][2] = *reinterpret_cast<const unsigned*>(Ab + 8);
            a[t][3] = *reinterpret_cast<const unsigned*>(Ab + 8 * 1024 + 8);
        }
#pragma unroll
        for (int u = 0; u < 4; u++) {
            const __half* Bb = BT + (size_t)(n0 + u * 8 + ra) * 1024 + k0 + kc;
            b[u][0] = *reinterpret_cast<const unsigned*>(Bb);
            b[u][1] = *reinterpret_cast<const unsigned*>(Bb + 8);
        }
#pragma unroll
        for (int t = 0; t < 2; t++)
#pragma unroll
            for (int u = 0; u < 4; u++)
                asm volatile(
                    "mma.sync.aligned.m16n8k16.row.col.f32.f16.f16.f32 "
                    "{%0,%1,%2,%3}, {%4,%5,%6,%7}, {%8,%9}, {%0,%1,%2,%3};"
                    : "+f"(d[t][u][0]), "+f"(d[t][u][1]), "+f"(d[t][u][2]), "+f"(d[t][u][3])
                    : "r"(a[t][0]), "r"(a[t][1]), "r"(a[t][2]), "r"(a[t][3]),
                      "r"(b[u][0]), "r"(b[u][1]));
    }
#pragma unroll
    for (int t = 0; t < 2; t++)
#pragma unroll
        for (int u = 0; u < 4; u++) {
            int r = m0 + t * 16 + ra, c = n0 + u * 8 + kc;
            *reinterpret_cast<__half2*>(C + (size_t)r * 1024 + c) =
                __floats2half2_rn(d[t][u][0], d[t][u][1]);
            *reinterpret_cast<__half2*>(C + (size_t)(r + 8) * 1024 + c) =
                __floats2half2_rn(d[t][u][2], d[t][u][3]);
        }
}

// ---------------- launch #4: main persistent kernel -----------------------------
__global__ void __launch_bounds__(NTHR, 1)
predcells_kernel(const float* __restrict__ x_seq,
                 const float* __restrict__ V1_b, const float* __restrict__ Vmid_b,
                 float* __restrict__ out) {
    __shared__ __align__(16) __half sbufA[2][2048];   // ping-pong [TD|h]
    __shared__ __align__(16) __half sh5[HH];          // top hidden (t-1), same-phase use
    __shared__ float sTD0[64];
    __shared__ float sred[32];

    const int tid  = threadIdx.x;
    const int lane = tid & 31;
    const int wid  = tid >> 5;
    const int gw   = blockIdx.x * (NTHR / 32) + wid;
    const int bgw  = gw - 32;                          // bg warp index (blocks 1..147)
    const long gtid = (long)blockIdx.x * NTHR + tid;
    const long gsz  = (long)NBLK * NTHR;

    float c_reg[5] = {0.f, 0.f, 0.f, 0.f, 0.f};
    unsigned ep = g_arrive[blockIdx.x * FLAGSTRIDE];

    // ---- prologue A: init state ----
    for (int i = tid; i < 4096; i += NTHR) (&sbufA[0][0])[i] = __ushort_as_half(0);
    for (long i = gtid; i < 4 * HH; i += gsz) (&g_reconR[0][0])[i] = __ushort_as_half(0);
    for (long i = gtid; i < 64; i += gsz) g_recon1[i] = __ushort_as_half(0);
    for (long i = gtid; i < 5 * 4096; i += gsz) (&g_G[0][0])[i] = (&d_gbase[0][0])[i];
    float td0p = 0.f;
    if (tid < CC) { td0p = fabsf(x_seq[tid]); sTD0[tid] = td0p; }
    bar_arrive(++ep);
    bar_wait(ep);

    // ---- prologue B: z_0(0) = F0*|x_0| + G_0 ----
    if (gw < 4096) {
        float a = warp_red(dot56h(&h_F0[(size_t)gw * 64], sTD0, lane));
        if (lane == 0) stf(&g_z[0][gw], a + ldf(&g_G[0][gw]));
    }
    bar_arrive(++ep);
    if (blockIdx.x == 0) {
        float s = block_sum(td0p, sred);
        if (tid == 0) stf(&g_loss_parts[0][0], s);
    }
    bar_wait(ep);

    int pp = 0;
    for (int t = 0; t < TT; t++) {
        // ================= phase 0: gates L0(t) + gates L4(t-1) ==================
        {
            __half* cur = &sbufA[pp][0];
            const __half* prv = &sbufA[pp ^ 1][0];   // [TD3(t-1) | h3(t-1)]
            float td;
            {
                const int k = tid;
                float zi = ldf(&g_z[0][k]);
                float zf = ldf(&g_z[0][1024 + k]);
                float zg = ldf(&g_z[0][2048 + k]);
                float zo = ldf(&g_z[0][3072 + k]);
                float cn = sigm(zf) * c_reg[0] + sigm(zi) * tanhf(zg);
                c_reg[0] = cn;
                float hn = sigm(zo) * tanhf(cn);
                td = fabsf(hn - ldh(&g_reconR[0][k]));
                cur[k] = __float2half_rn(td);
                cur[1024 + k] = __float2half_rn(hn);
                if (t > 0) {   // top-layer gates for step t-1
                    float ti = ldf(&g_z[4][k]);
                    float tf = ldf(&g_z[4][1024 + k]);
                    float tg = ldf(&g_z[4][2048 + k]);
                    float to = ldf(&g_z[4][3072 + k]);
                    float tc = sigm(tf) * c_reg[4] + sigm(ti) * tanhf(tg);
                    c_reg[4] = tc;
                    sh5[k] = __float2half_rn(sigm(to) * tanhf(tc));
                } else {
                    sh5[k] = __ushort_as_half(0);
                }
            }
            __syncthreads();
            if (gw < 4096) {     // chain: z1 = F[0]*TD0 + G1
                float a = warp_red(dot16<2048>(&h_F[0][(size_t)gw * 1024], cur, lane));
                if (lane == 0) stf(&g_z[1][gw], a + ldf(&g_G[1][gw]));
            }
            bar_arrive(++ep);
            if (blockIdx.x > 0) {
                bg_p0(bgw, lane, t, sh5, prv, Vmid_b);
            } else {
                float s = block_sum(td, sred);
                if (tid == 0) stf(&g_loss_parts[t][1], s);
            }
            bar_wait(ep);
            pp ^= 1;
        }

        // ================= phases 1..2: mid layers ===============================
#pragma unroll 1
        for (int ph = 1; ph <= 2; ph++) {
            __half* cur = &sbufA[pp][0];
            const __half* prv = &sbufA[pp ^ 1][0];
            float td;
            {
                const int k = tid;
                float zi = ldf(&g_z[ph][k]);
                float zf = ldf(&g_z[ph][1024 + k]);
                float zg = ldf(&g_z[ph][2048 + k]);
                float zo = ldf(&g_z[ph][3072 + k]);
                float cn = sigm(zf) * c_reg[ph] + sigm(zi) * tanhf(zg);
                c_reg[ph] = cn;
                float hn = sigm(zo) * tanhf(cn);
                td = fabsf(hn - ldh(&g_reconR[ph][k]));
                cur[k] = __float2half_rn(td);
                cur[1024 + k] = __float2half_rn(hn);
            }
            __syncthreads();
            if (gw < 4096) {
                float a = warp_red(dot16<2048>(&h_F[ph][(size_t)gw * 1024], cur, lane));
                if (lane == 0) stf(&g_z[ph + 1][gw], a + ldf(&g_G[ph + 1][gw]));
            }
            bar_arrive(++ep);
            if (blockIdx.x > 0) {
                if (ph == 1)
                    bg_work(bgw, lane, &w8_G[0][0], prv, g_G[0], d_gbase[0],
                            56, h_V1, prv + 1024, g_recon1, V1_b);
                else
                    bg_work(bgw, lane, &w8_G[1][0], prv, g_G[1], d_gbase[1],
                            1024, h_Vmid, prv + 1024, g_reconR[0], Vmid_b);
            } else {
                float s = block_sum(td, sred);
                if (tid == 0) stf(&g_loss_parts[t][1 + ph], s);
            }
            bar_wait(ep);
            pp ^= 1;
        }

        // ================= phase 3: gates L3 + dual chain (z4, z0(t+1)) ==========
        {
            const bool more = (t + 1 < TT);
            __half* cur = &sbufA[pp][0];
            const __half* prv = &sbufA[pp ^ 1][0];   // [TD2 | h2]
            float td;
            {
                const int k = tid;
                float zi = ldf(&g_z[3][k]);
                float zf = ldf(&g_z[3][1024 + k]);
                float zg = ldf(&g_z[3][2048 + k]);
                float zo = ldf(&g_z[3][3072 + k]);
                float cn = sigm(zf) * c_reg[3] + sigm(zi) * tanhf(zg);
                c_reg[3] = cn;
                float hn = sigm(zo) * tanhf(cn);
                td = fabsf(hn - ldh(&g_reconR[3][k]));
                cur[k] = __float2half_rn(td);
                cur[1024 + k] = __float2half_rn(hn);
            }
            float td0 = 0.f;
            if (more && tid < CC) {
                td0 = fabsf(x_seq[(t + 1) * CC + tid] - ldh(&g_recon1[tid]));
                sTD0[tid] = td0;
            }
            __syncthreads();
            if (gw < 4096) {
                float a = warp_red(dot16<2048>(&h_F[3][(size_t)gw * 1024], cur, lane));
                if (lane == 0) stf(&g_z[4][gw], a + ldf(&g_G[4][gw]));
                if (more) {
                    float b = warp_red(dot56h(&h_F0[(size_t)gw * 64], sTD0, lane));
                    if (lane == 0) stf(&g_z[0][gw], b + ldf(&g_G[0][gw]));
                }
            }
            bar_arrive(++ep);
            if (blockIdx.x > 0) {
                bg_work(bgw, lane, &w8_G[2][0], prv, g_G[2], d_gbase[2],
                        1024, h_Vmid + (size_t)1048576, prv + 1024, g_reconR[1], Vmid_b + 1024);
            } else {
                float s = block_sum(td, sred);
                if (tid == 0) stf(&g_loss_parts[t][4], s);
                float s0 = block_sum(td0, sred);
                if (more && tid == 0) stf(&g_loss_parts[t + 1][0], s0);
            }
            bar_wait(ep);
            pp ^= 1;
        }
    }

    // ---- epilogue: deterministic loss reduction ----
    if (blockIdx.x == 0) {
        const float* parts = &g_loss_parts[0][0];
        float v = 0.f;
        for (int i = tid; i < TT * 5; i += NTHR) v += ldf(&parts[i]);
        float s = block_sum(v, sred);
        if (tid == 0) out[0] = s;
    }
}

// ---------------- launch (4 kernels: predcells is global launch #4) --------------
extern "C" void kernel_launch(void* const* d_in, const int* in_sizes, int n_in,
                              void* d_out, int out_size) {
    (void)in_sizes; (void)n_in; (void)out_size;
    const float* x_seq  = (const float*)d_in[0];
    const float* W0_w   = (const float*)d_in[1];
    const float* W0_b   = (const float*)d_in[2];
    const float* Wmid_w = (const float*)d_in[3];
    const float* Wmid_b = (const float*)d_in[4];
    const float* V1_w   = (const float*)d_in[5];
    const float* V1_b   = (const float*)d_in[6];
    const float* Vmid_w = (const float*)d_in[7];
    const float* Vmid_b = (const float*)d_in[8];
    const float* Wihm   = (const float*)d_in[9];
    const float* Whhm   = (const float*)d_in[10];
    const float* bmid   = (const float*)d_in[11];
    const float* Wiht   = (const float*)d_in[12];
    const float* Whht   = (const float*)d_in[13];
    const float* btop   = (const float*)d_in[14];

    conv_ab<<<2048, 256>>>(Wihm, Wiht, Wmid_w);
    prep_merged<<<3072, 256>>>(Wihm, Wiht, W0_b, Wmid_b, bmid, btop,
                               V1_w, Vmid_w, Whhm, Whht, W0_w);
    gemm_fold_mma<<<dim3(16, 32, 4), 256>>>();
    predcells_kernel<<<NBLK, NTHR>>>(x_seq, V1_b, Vmid_b, (float*)d_out);
}

// round 16
// speedup vs baseline: 1.0494x; 1.0421x over previous
#include <cuda_runtime.h>
#include <cuda_fp16.h>
#include <cuda_fp8.h>

#define TT 256
#define CC 56
#define HH 1024
#define NBLK 148
#define NTHR 1024
#define NBGW 4704                /* bg warps: blocks 1..147 x 32 */
#define INV_WSCALE (1.0f/64.0f)

// ---------------- folded / quantized weights (built per launch) ----------------
__device__ __align__(16) __half  h_F[4][(size_t)4096*1024];   // F_{m->m+1} fp16
__device__ __align__(16) __half  h_F0[(size_t)4096*64];       // Wih0[:,:H]*W0
__device__ __align__(16) unsigned char w8_G[4][(size_t)4096*2048]; // [Wih[:,H:]|Whh] fp8
__device__ __align__(16) unsigned char w8_Gtop[(size_t)4096*1024]; // Whh_top fp8
__device__ __align__(16) __half  h_Vmid[(size_t)4*1024*1024];
__device__ __align__(16) __half  h_V1[(size_t)56*1024];
__device__ float d_gbase[5][4096];

// fp16 staging for the tensor-core fold GEMM
__device__ __align__(16) __half  h_A16[(size_t)4*4096*1024];
__device__ __align__(16) __half  h_BT[(size_t)4*1024*1024];

// ---------------- runtime state ------------------------------------------------
__device__ __align__(16) float g_z[5][4096];   // interleaved layout [k*4+gate]
__device__ float g_G[5][4096];                 // row-indexed (read scalar at chain)
__device__ __align__(4) __half g_reconR[4][HH];
__device__ __align__(4) __half g_recon1[64];
__device__ float g_loss_parts[TT][5];
__device__ unsigned g_arrive[NBLK];

// ---------------- helpers ------------------------------------------------------
__device__ __forceinline__ float ldf(const float* p) { return __ldcg(p); }
__device__ __forceinline__ void  stf(float* p, float v) { __stcg(p, v); }
__device__ __forceinline__ float ldh(const __half* p) {
    unsigned short u = __ldcg(reinterpret_cast<const unsigned short*>(p));
    return __half2float(__ushort_as_half(u));
}
__device__ __forceinline__ void sth(__half* p, float v) {
    __stcg(reinterpret_cast<unsigned short*>(p), __half_as_ushort(__float2half_rn(v)));
}
__device__ __forceinline__ int il(int r) { return ((r & 1023) << 2) | (r >> 10); }

__device__ __forceinline__ float warp_red(float v) {
#pragma unroll
    for (int o = 16; o; o >>= 1) v += __shfl_xor_sync(0xffffffffu, v, o);
    return v;
}

__device__ __forceinline__ __half2 cvt8(unsigned v16) {
    __half2_raw r = __nv_cvt_fp8x2_to_halfraw2((__nv_fp8x2_storage_t)v16, __NV_E4M3);
    return *reinterpret_cast<__half2*>(&r);
}
__device__ __forceinline__ float hsum(__half2 h) {
    float2 f = __half22float2(h);
    return f.x + f.y;
}

template<int NB>
__device__ __forceinline__ float dot8(const unsigned char* __restrict__ w,
                                      const __half* __restrict__ x, int lane) {
    float acc = 0.f;
#pragma unroll
    for (int it = 0; it < NB / 512; it++) {
        int c = it * 512 + lane * 16;
        uint4 wv  = *reinterpret_cast<const uint4*>(w + c);
        uint4 xv0 = *reinterpret_cast<const uint4*>(reinterpret_cast<const char*>(x) + 2 * c);
        uint4 xv1 = *reinterpret_cast<const uint4*>(reinterpret_cast<const char*>(x) + 2 * c + 16);
        const __half2* xa = reinterpret_cast<const __half2*>(&xv0);
        const __half2* xb = reinterpret_cast<const __half2*>(&xv1);
        __half2 s = __floats2half2_rn(0.f, 0.f);
        s = __hfma2(cvt8(wv.x & 0xffffu), xa[0], s);
        s = __hfma2(cvt8(wv.x >> 16),     xa[1], s);
        s = __hfma2(cvt8(wv.y & 0xffffu), xa[2], s);
        s = __hfma2(cvt8(wv.y >> 16),     xa[3], s);
        s = __hfma2(cvt8(wv.z & 0xffffu), xb[0], s);
        s = __hfma2(cvt8(wv.z >> 16),     xb[1], s);
        s = __hfma2(cvt8(wv.w & 0xffffu), xb[2], s);
        s = __hfma2(cvt8(wv.w >> 16),     xb[3], s);
        acc += hsum(s);
    }
    return acc;
}

// dual-row fp8 dot: rows share the x vector; weight loads interleaved for MLP.
// Per-row arithmetic order identical to dot8.
template<int NB>
__device__ __forceinline__ float2 dot8x2(const unsigned char* __restrict__ w0,
                                         const unsigned char* __restrict__ w1,
                                         const __half* __restrict__ x, int lane) {
    float a0 = 0.f, a1 = 0.f;
#pragma unroll
    for (int it = 0; it < NB / 512; it++) {
        int c = it * 512 + lane * 16;
        uint4 wv0 = *reinterpret_cast<const uint4*>(w0 + c);
        uint4 wv1 = *reinterpret_cast<const uint4*>(w1 + c);
        uint4 xv0 = *reinterpret_cast<const uint4*>(reinterpret_cast<const char*>(x) + 2 * c);
        uint4 xv1 = *reinterpret_cast<const uint4*>(reinterpret_cast<const char*>(x) + 2 * c + 16);
        const __half2* xa = reinterpret_cast<const __half2*>(&xv0);
        const __half2* xb = reinterpret_cast<const __half2*>(&xv1);
        __half2 s0 = __floats2half2_rn(0.f, 0.f);
        s0 = __hfma2(cvt8(wv0.x & 0xffffu), xa[0], s0);
        s0 = __hfma2(cvt8(wv0.x >> 16),     xa[1], s0);
        s0 = __hfma2(cvt8(wv0.y & 0xffffu), xa[2], s0);
        s0 = __hfma2(cvt8(wv0.y >> 16),     xa[3], s0);
        s0 = __hfma2(cvt8(wv0.z & 0xffffu), xb[0], s0);
        s0 = __hfma2(cvt8(wv0.z >> 16),     xb[1], s0);
        s0 = __hfma2(cvt8(wv0.w & 0xffffu), xb[2], s0);
        s0 = __hfma2(cvt8(wv0.w >> 16),     xb[3], s0);
        a0 += hsum(s0);
        __half2 s1 = __floats2half2_rn(0.f, 0.f);
        s1 = __hfma2(cvt8(wv1.x & 0xffffu), xa[0], s1);
        s1 = __hfma2(cvt8(wv1.x >> 16),     xa[1], s1);
        s1 = __hfma2(cvt8(wv1.y & 0xffffu), xa[2], s1);
        s1 = __hfma2(cvt8(wv1.y >> 16),     xa[3], s1);
        s1 = __hfma2(cvt8(wv1.z & 0xffffu), xb[0], s1);
        s1 = __hfma2(cvt8(wv1.z >> 16),     xb[1], s1);
        s1 = __hfma2(cvt8(wv1.w & 0xffffu), xb[2], s1);
        s1 = __hfma2(cvt8(wv1.w >> 16),     xb[3], s1);
        a1 += hsum(s1);
    }
    return make_float2(a0, a1);
}

template<int NB>
__device__ __forceinline__ float dot16(const __half* __restrict__ w,
                                       const __half* __restrict__ x, int lane) {
    float acc = 0.f;
#pragma unroll
    for (int it = 0; it < NB / 512; it++) {
        int c = it * 512 + lane * 16;
        uint4 wv = *reinterpret_cast<const uint4*>(reinterpret_cast<const char*>(w) + c);
        uint4 xv = *reinterpret_cast<const uint4*>(reinterpret_cast<const char*>(x) + c);
        const __half2* wa = reinterpret_cast<const __half2*>(&wv);
        const __half2* xa = reinterpret_cast<const __half2*>(&xv);
        __half2 s = __floats2half2_rn(0.f, 0.f);
        s = __hfma2(wa[0], xa[0], s);
        s = __hfma2(wa[1], xa[1], s);
        s = __hfma2(wa[2], xa[2], s);
        s = __hfma2(wa[3], xa[3], s);
        acc += hsum(s);
    }
    return acc;
}

__device__ __forceinline__ float dot56h(const __half* __restrict__ w,
                                        const float* __restrict__ x, int lane) {
    float acc = 0.f;
    if (lane < 28) {
        __half2 h = *reinterpret_cast<const __half2*>(w + lane * 2);
        float2 f = __half22float2(h);
        acc = f.x * x[lane * 2] + f.y * x[lane * 2 + 1];
    }
    return acc;
}

__device__ __forceinline__ float sigm(float x) { return 1.f / (1.f + __expf(-x)); }

// ---- split grid barrier: arrive (release) / wait (warp-scan acquire) ----------
__device__ __forceinline__ void bar_arrive(unsigned ep) {
    __syncthreads();
    if (threadIdx.x == 0)
        asm volatile("st.release.gpu.global.b32 [%0], %1;"
                     :: "l"(g_arrive + blockIdx.x), "r"(ep) : "memory");
}
__device__ __forceinline__ void bar_wait(unsigned ep) {
    if (threadIdx.x < 32) {
        const int lane = threadIdx.x;
        bool done = false;
        while (!done) {
            bool ok = true;
#pragma unroll
            for (int j = 0; j < 5; j++) {
                int s = lane + j * 32;
                if (s < NBLK) {
                    unsigned v;
                    asm volatile("ld.acquire.gpu.global.b32 %0, [%1];"
                                 : "=r"(v) : "l"(g_arrive + s) : "memory");
                    ok &= ((int)(v - ep) >= 0);
                }
            }
            done = __all_sync(0xffffffffu, ok);
        }
    }
    __syncthreads();
}

__device__ __forceinline__ float block_sum(float v, float* sred) {
    int lane = threadIdx.x & 31, w = threadIdx.x >> 5;
    v = warp_red(v);
    if (lane == 0) sred[w] = v;
    __syncthreads();
    float r = 0.f;
    if (w == 0) {
        r = (lane < NTHR / 32) ? sred[lane] : 0.f;
        r = warp_red(r);
    }
    __syncthreads();
    return r;
}

// Standard bg (blocks 1..147): 2048 G-row PAIRS + nv V singles; all warps <=1 task.
__device__ __forceinline__ void bg_work(int bgw, int lane,
                                        const unsigned char* __restrict__ gwts,
                                        const __half* __restrict__ gin,
                                        float* __restrict__ gout,
                                        const float* __restrict__ gbase,
                                        int nv,
                                        const __half* __restrict__ vwts,
                                        const __half* __restrict__ vin,
                                        __half* __restrict__ vout,
                                        const float* __restrict__ vbias) {
    if (bgw < 2048) {
        int r0 = bgw * 2, r1 = r0 + 1;
        float2 a = dot8x2<2048>(gwts + (size_t)r0 * 2048, gwts + (size_t)r1 * 2048, gin, lane);
        a.x = warp_red(a.x);
        a.y = warp_red(a.y);
        if (lane == 0) {
            stf(&gout[r0], a.x * INV_WSCALE + gbase[r0]);
            stf(&gout[r1], a.y * INV_WSCALE + gbase[r1]);
        }
    } else if (bgw < 2048 + nv) {
        int v = bgw - 2048;
        float a = warp_red(dot16<2048>(vwts + (size_t)v * 1024, vin, lane));
        if (lane == 0) sth(&vout[v], a + vbias[v]);
    }
}

// Heavy P0 bg: Gtop pairs (2048) + G3 pairs (2048) + rec3 (1024) + rec2 (1024).
__device__ __forceinline__ void bg_p0(int bgw, int lane, int t,
                                      const __half* __restrict__ sh5,
                                      const __half* __restrict__ prv,
                                      const float* __restrict__ Vmid_b) {
    const int vmax = (t > 0) ? 6144 : 4096;   // skip recon writes at t=0 (zero carry)
    for (int task = bgw; task < vmax; task += NBGW) {
        if (task < 2048) {
            int r0 = task * 2, r1 = r0 + 1;
            float2 a = dot8x2<1024>(w8_Gtop + (size_t)r0 * 1024, w8_Gtop + (size_t)r1 * 1024, sh5, lane);
            a.x = warp_red(a.x);
            a.y = warp_red(a.y);
            if (lane == 0) {
                stf(&g_G[4][r0], a.x * INV_WSCALE + d_gbase[4][r0]);
                stf(&g_G[4][r1], a.y * INV_WSCALE + d_gbase[4][r1]);
            }
        } else if (task < 4096) {
            int r0 = (task - 2048) * 2, r1 = r0 + 1;
            float2 a = dot8x2<2048>(&w8_G[3][(size_t)r0 * 2048], &w8_G[3][(size_t)r1 * 2048], prv, lane);
            a.x = warp_red(a.x);
            a.y = warp_red(a.y);
            if (lane == 0) {
                stf(&g_G[3][r0], a.x * INV_WSCALE + d_gbase[3][r0]);
                stf(&g_G[3][r1], a.y * INV_WSCALE + d_gbase[3][r1]);
            }
        } else if (task < 5120) {
            int v = task - 4096;
            float a = warp_red(dot16<2048>(h_Vmid + (size_t)3 * 1048576 + (size_t)v * 1024, sh5, lane));
            if (lane == 0) sth(&g_reconR[3][v], a + Vmid_b[3072 + v]);
        } else {
            int v = task - 5120;
            float a = warp_red(dot16<2048>(h_Vmid + (size_t)2 * 1048576 + (size_t)v * 1024, prv + 1024, lane));
            if (lane == 0) sth(&g_reconR[2][v], a + Vmid_b[2048 + v]);
        }
    }
}

// ---------------- pre-pass 0: fp16 staging for the fold GEMM --------------------
__global__ void conv_ab(const float* __restrict__ Wihm, const float* __restrict__ Wiht,
                        const float* __restrict__ Wmid) {
    long i0 = (long)blockIdx.x * blockDim.x + threadIdx.x;
    long st = (long)gridDim.x * blockDim.x;
    for (long i = i0; i < 4L * 4096 * 256; i += st) {
        long zr = i >> 8;
        int z = (int)(zr >> 12);
        long r = zr & 4095;
        int cc = (int)(i & 255) * 4;
        const float* src = (z < 3) ? (Wihm + ((size_t)(z + 1) * 4096 + r) * 2048 + cc)
                                   : (Wiht + (size_t)r * 1024 + cc);
        float4 v = *reinterpret_cast<const float4*>(src);
        *reinterpret_cast<__half2*>(h_A16 + zr * 1024 + cc)     = __floats2half2_rn(v.x, v.y);
        *reinterpret_cast<__half2*>(h_A16 + zr * 1024 + cc + 2) = __floats2half2_rn(v.z, v.w);
    }
    for (long i = i0; i < 4L * 1024 * 1024; i += st) {
        long z = i >> 20;
        int ii = (int)((i >> 10) & 1023);
        int j  = (int)(i & 1023);
        h_BT[z * 1048576 + (size_t)j * 1024 + ii] =
            __float2half_rn(Wmid[z * 1048576 + (size_t)ii * 1024 + j]);
    }
}

// ---------------- pre-pass 1: fold GEMM via mma.sync (HMMA, fp16 out) -----------
__global__ void gemm_fold_mma() {
    const int z = blockIdx.z;
    const __half* A  = h_A16 + (size_t)z * 4096 * 1024;
    const __half* BT = h_BT  + (size_t)z * 1024 * 1024;
    __half* C = &h_F[z][0];
    const int wid = threadIdx.x >> 5, lane = threadIdx.x & 31;
    const int wm = wid >> 1, wn = wid & 1;
    const int m0 = blockIdx.y * 128 + wm * 32;
    const int n0 = blockIdx.x * 64 + wn * 32;
    const int ra = lane >> 2, kc = (lane & 3) * 2;
    float d[2][4][4] = {};
    for (int k0 = 0; k0 < 1024; k0 += 16) {
        unsigned a[2][4], b[4][2];
#pragma unroll
        for (int t = 0; t < 2; t++) {
            const __half* Ab = A + (size_t)(m0 + t * 16 + ra) * 1024 + k0 + kc;
            a[t][0] = *reinterpret_cast<const unsigned*>(Ab);
            a[t][1] = *reinterpret_cast<const unsigned*>(Ab + 8 * 1024);
            a[t][2] = *reinterpret_cast<const unsigned*>(Ab + 8);
            a[t][3] = *reinterpret_cast<const unsigned*>(Ab + 8 * 1024 + 8);
        }
#pragma unroll
        for (int u = 0; u < 4; u++) {
            const __half* Bb = BT + (size_t)(n0 + u * 8 + ra) * 1024 + k0 + kc;
            b[u][0] = *reinterpret_cast<const unsigned*>(Bb);
            b[u][1] = *reinterpret_cast<const unsigned*>(Bb + 8);
        }
#pragma unroll
        for (int t = 0; t < 2; t++)
#pragma unroll
            for (int u = 0; u < 4; u++)
                asm volatile(
                    "mma.sync.aligned.m16n8k16.row.col.f32.f16.f16.f32 "
                    "{%0,%1,%2,%3}, {%4,%5,%6,%7}, {%8,%9}, {%0,%1,%2,%3};"
                    : "+f"(d[t][u][0]), "+f"(d[t][u][1]), "+f"(d[t][u][2]), "+f"(d[t][u][3])
                    : "r"(a[t][0]), "r"(a[t][1]), "r"(a[t][2]), "r"(a[t][3]),
                      "r"(b[u][0]), "r"(b[u][1]));
    }
#pragma unroll
    for (int t = 0; t < 2; t++)
#pragma unroll
        for (int u = 0; u < 4; u++) {
            int r = m0 + t * 16 + ra, c = n0 + u * 8 + kc;
            *reinterpret_cast<__half2*>(C + (size_t)r * 1024 + c) =
                __floats2half2_rn(d[t][u][0], d[t][u][1]);
            *reinterpret_cast<__half2*>(C + (size_t)(r + 8) * 1024 + c) =
                __floats2half2_rn(d[t][u][2], d[t][u][3]);
        }
}

// ---------------- pre-pass 2: F0 = Wih0[:,:H] x W0 ------------------------------
__global__ void f0_fold(const float* __restrict__ Wihm, const float* __restrict__ W0w) {
    int wid = threadIdx.x >> 5, lane = threadIdx.x & 31;
    int r = blockIdx.x * 8 + wid;
    float a[32];
    const float* Arow = Wihm + (size_t)r * 2048;
#pragma unroll
    for (int j = 0; j < 32; j++) a[j] = Arow[lane + 32 * j];
    for (int c = 0; c < CC; c++) {
        float s = 0.f;
#pragma unroll
        for (int j = 0; j < 32; j++) s = fmaf(a[j], W0w[(lane + 32 * j) * CC + c], s);
        s = warp_red(s);
        if (lane == 0) h_F0[(size_t)r * 64 + c] = __float2half_rn(s);
    }
}

// ---------------- pre-pass 3 (merged): gbase + quantize/pack --------------------
__global__ void gbase_convert(const float* __restrict__ Wihm, const float* __restrict__ Wiht,
                              const float* __restrict__ W0_b, const float* __restrict__ Wmid_b,
                              const float* __restrict__ bmid, const float* __restrict__ btop,
                              const float* __restrict__ V1, const float* __restrict__ Vmid,
                              const float* __restrict__ Whhm, const float* __restrict__ Whht) {
    int gwarp = (blockIdx.x * blockDim.x + threadIdx.x) >> 5;
    int lane = threadIdx.x & 31;
    if (gwarp < 5 * 4096) {
        int lay = gwarp >> 12;
        int r = gwarp & 4095;
        const float* Arow;
        const float* bv;
        float bias;
        if (lay < 4) {
            Arow = Wihm + ((size_t)lay * 4096 + r) * 2048;
            bv = (lay == 0) ? W0_b : (Wmid_b + (lay - 1) * 1024);
            bias = bmid[lay * 4096 + r];
        } else {
            Arow = Wiht + (size_t)r * 1024;
            bv = Wmid_b + 3 * 1024;
            bias = btop[r];
        }
        float s = 0.f;
        for (int j = lane; j < 1024; j += 32) s = fmaf(Arow[j], bv[j], s);
        s = warp_red(s);
        if (lane == 0) d_gbase[lay][r] = s + bias;
    }
    long i0 = (long)blockIdx.x * blockDim.x + threadIdx.x;
    long st = (long)gridDim.x * blockDim.x;
#define PACK8(v) ( (unsigned)__nv_cvt_float2_to_fp8x2(make_float2((v).x*64.f,(v).y*64.f), __NV_SATFINITE, __NV_E4M3) \
                 | ((unsigned)__nv_cvt_float2_to_fp8x2(make_float2((v).z*64.f,(v).w*64.f), __NV_SATFINITE, __NV_E4M3) << 16) )
    for (long i = i0; i < 16384L * 256; i += st) {
        long row = i >> 8; int jj = (int)(i & 255) * 4;
        float4 v = *reinterpret_cast<const float4*>(Wihm + row * 2048 + 1024 + jj);
        reinterpret_cast<unsigned*>(&w8_G[0][0])[row * 512 + (jj >> 2)] = PACK8(v);
    }
    for (long i = i0; i < 16384L * 256; i += st) {
        long row = i >> 8; int jj = (int)(i & 255) * 4;
        float4 v = *reinterpret_cast<const float4*>(Whhm + row * 1024 + jj);
        reinterpret_cast<unsigned*>(&w8_G[0][0])[row * 512 + 256 + (jj >> 2)] = PACK8(v);
    }
    for (long i = i0; i < 4096L * 256; i += st) {
        float4 v = *reinterpret_cast<const float4*>(Whht + i * 4);
        reinterpret_cast<unsigned*>(w8_Gtop)[i] = PACK8(v);
    }
#undef PACK8
    for (long i = i0; i < 4L * 1024 * 1024 / 2; i += st)
        reinterpret_cast<__half2*>(h_Vmid)[i] = __float22half2_rn(reinterpret_cast<const float2*>(Vmid)[i]);
    for (long i = i0; i < 56L * 1024 / 2; i += st)
        reinterpret_cast<__half2*>(h_V1)[i] = __float22half2_rn(reinterpret_cast<const float2*>(V1)[i]);
}

// ---------------- main persistent kernel ----------------------------------------
__global__ void __launch_bounds__(NTHR, 1)
predcells_kernel(const float* __restrict__ x_seq,
                 const float* __restrict__ V1_b, const float* __restrict__ Vmid_b,
                 float* __restrict__ out) {
    __shared__ __align__(16) __half sbufA[2][2048];   // ping-pong [TD|h]
    __shared__ __align__(16) __half sh5[HH];          // top hidden (t-1), same-phase use
    __shared__ float sTD0[64];
    __shared__ float sred[32];

    const int tid  = threadIdx.x;
    const int lane = tid & 31;
    const int wid  = tid >> 5;
    const int gw   = blockIdx.x * (NTHR / 32) + wid;
    const int bgw  = gw - 32;                          // bg warp index (blocks 1..147)
    const long gtid = (long)blockIdx.x * NTHR + tid;
    const long gsz  = (long)NBLK * NTHR;

    float c_reg[5] = {0.f, 0.f, 0.f, 0.f, 0.f};
    unsigned ep = g_arrive[blockIdx.x];

    // ---- prologue A: init state ----
    for (int i = tid; i < 4096; i += NTHR) (&sbufA[0][0])[i] = __ushort_as_half(0);
    for (long i = gtid; i < 4 * HH; i += gsz) (&g_reconR[0][0])[i] = __ushort_as_half(0);
    for (long i = gtid; i < 64; i += gsz) g_recon1[i] = __ushort_as_half(0);
    for (long i = gtid; i < 5 * 4096; i += gsz) (&g_G[0][0])[i] = (&d_gbase[0][0])[i];
    float td0p = 0.f;
    if (tid < CC) { td0p = fabsf(x_seq[tid]); sTD0[tid] = td0p; }
    bar_arrive(++ep);
    bar_wait(ep);

    // ---- prologue B: z_0(0) = F0*|x_0| + G_0 (interleaved store) ----
    if (gw < 4096) {
        float a = warp_red(dot56h(&h_F0[(size_t)gw * 64], sTD0, lane));
        if (lane == 0) stf(&g_z[0][il(gw)], a + ldf(&g_G[0][gw]));
    }
    bar_arrive(++ep);
    if (blockIdx.x == 0) {
        float s = block_sum(td0p, sred);
        if (tid == 0) stf(&g_loss_parts[0][0], s);
    }
    bar_wait(ep);

    int pp = 0;
    for (int t = 0; t < TT; t++) {
        // ================= phase 0: gates L0(t) + gates L4(t-1) ==================
        {
            __half* cur = &sbufA[pp][0];
            const __half* prv = &sbufA[pp ^ 1][0];   // [TD3(t-1) | h3(t-1)]
            float td;
            {
                const int k = tid;
                float4 zv = __ldcg(reinterpret_cast<const float4*>(&g_z[0][k << 2]));
                float cn = sigm(zv.y) * c_reg[0] + sigm(zv.x) * tanhf(zv.z);
                c_reg[0] = cn;
                float hn = sigm(zv.w) * tanhf(cn);
                td = fabsf(hn - ldh(&g_reconR[0][k]));
                cur[k] = __float2half_rn(td);
                cur[1024 + k] = __float2half_rn(hn);
                if (t > 0) {   // top-layer gates for step t-1
                    float4 z4 = __ldcg(reinterpret_cast<const float4*>(&g_z[4][k << 2]));
                    float tc = sigm(z4.y) * c_reg[4] + sigm(z4.x) * tanhf(z4.z);
                    c_reg[4] = tc;
                    sh5[k] = __float2half_rn(sigm(z4.w) * tanhf(tc));
                } else {
                    sh5[k] = __ushort_as_half(0);
                }
            }
            __syncthreads();
            if (gw < 4096) {     // chain: z1 = F[0]*TD0 + G1
                float a = warp_red(dot16<2048>(&h_F[0][(size_t)gw * 1024], cur, lane));
                if (lane == 0) stf(&g_z[1][il(gw)], a + ldf(&g_G[1][gw]));
            }
            bar_arrive(++ep);
            if (blockIdx.x > 0) {
                bg_p0(bgw, lane, t, sh5, prv, Vmid_b);
            } else {
                float s = block_sum(td, sred);
                if (tid == 0) stf(&g_loss_parts[t][1], s);
            }
            bar_wait(ep);
            pp ^= 1;
        }

        // ================= phases 1..2: mid layers ===============================
#pragma unroll 1
        for (int ph = 1; ph <= 2; ph++) {
            __half* cur = &sbufA[pp][0];
            const __half* prv = &sbufA[pp ^ 1][0];
            float td;
            {
                const int k = tid;
                float4 zv = __ldcg(reinterpret_cast<const float4*>(&g_z[ph][k << 2]));
                float cn = sigm(zv.y) * c_reg[ph] + sigm(zv.x) * tanhf(zv.z);
                c_reg[ph] = cn;
                float hn = sigm(zv.w) * tanhf(cn);
                td = fabsf(hn - ldh(&g_reconR[ph][k]));
                cur[k] = __float2half_rn(td);
                cur[1024 + k] = __float2half_rn(hn);
            }
            __syncthreads();
            if (gw < 4096) {
                float a = warp_red(dot16<2048>(&h_F[ph][(size_t)gw * 1024], cur, lane));
                if (lane == 0) stf(&g_z[ph + 1][il(gw)], a + ldf(&g_G[ph + 1][gw]));
            }
            bar_arrive(++ep);
            if (blockIdx.x > 0) {
                if (ph == 1)
                    bg_work(bgw, lane, &w8_G[0][0], prv, g_G[0], d_gbase[0],
                            56, h_V1, prv + 1024, g_recon1, V1_b);
                else
                    bg_work(bgw, lane, &w8_G[1][0], prv, g_G[1], d_gbase[1],
                            1024, h_Vmid, prv + 1024, g_reconR[0], Vmid_b);
            } else {
                float s = block_sum(td, sred);
                if (tid == 0) stf(&g_loss_parts[t][1 + ph], s);
            }
            bar_wait(ep);
            pp ^= 1;
        }

        // ================= phase 3: gates L3 + dual chain (z4, z0(t+1)) ==========
        {
            const bool more = (t + 1 < TT);
            __half* cur = &sbufA[pp][0];
            const __half* prv = &sbufA[pp ^ 1][0];   // [TD2 | h2]
            float td;
            {
                const int k = tid;
                float4 zv = __ldcg(reinterpret_cast<const float4*>(&g_z[3][k << 2]));
                float cn = sigm(zv.y) * c_reg[3] + sigm(zv.x) * tanhf(zv.z);
                c_reg[3] = cn;
                float hn = sigm(zv.w) * tanhf(cn);
                td = fabsf(hn - ldh(&g_reconR[3][k]));
                cur[k] = __float2half_rn(td);
                cur[1024 + k] = __float2half_rn(hn);
            }
            float td0 = 0.f;
            if (more && tid < CC) {
                td0 = fabsf(x_seq[(t + 1) * CC + tid] - ldh(&g_recon1[tid]));
                sTD0[tid] = td0;
            }
            __syncthreads();
            if (gw < 4096) {
                float a = warp_red(dot16<2048>(&h_F[3][(size_t)gw * 1024], cur, lane));
                if (lane == 0) stf(&g_z[4][il(gw)], a + ldf(&g_G[4][gw]));
                if (more) {
                    float b = warp_red(dot56h(&h_F0[(size_t)gw * 64], sTD0, lane));
                    if (lane == 0) stf(&g_z[0][il(gw)], b + ldf(&g_G[0][gw]));
                }
            }
            bar_arrive(++ep);
            if (blockIdx.x > 0) {
                bg_work(bgw, lane, &w8_G[2][0], prv, g_G[2], d_gbase[2],
                        1024, h_Vmid + (size_t)1048576, prv + 1024, g_reconR[1], Vmid_b + 1024);
            } else {
                float s = block_sum(td, sred);
                if (tid == 0) stf(&g_loss_parts[t][4], s);
                float s0 = block_sum(td0, sred);
                if (more && tid == 0) stf(&g_loss_parts[t + 1][0], s0);
            }
            bar_wait(ep);
            pp ^= 1;
        }
    }

    // ---- epilogue: deterministic loss reduction ----
    if (blockIdx.x == 0) {
        const float* parts = &g_loss_parts[0][0];
        float v = 0.f;
        for (int i = tid; i < TT * 5; i += NTHR) v += ldf(&parts[i]);
        float s = block_sum(v, sred);
        if (tid == 0) out[0] = s;
    }
}

// ---------------- launch (R13 structure) -----------------------------------------
extern "C" void kernel_launch(void* const* d_in, const int* in_sizes, int n_in,
                              void* d_out, int out_size) {
    (void)in_sizes; (void)n_in; (void)out_size;
    const float* x_seq  = (const float*)d_in[0];
    const float* W0_w   = (const float*)d_in[1];
    const float* W0_b   = (const float*)d_in[2];
    const float* Wmid_w = (const float*)d_in[3];
    const float* Wmid_b = (const float*)d_in[4];
    const float* V1_w   = (const float*)d_in[5];
    const float* V1_b   = (const float*)d_in[6];
    const float* Vmid_w = (const float*)d_in[7];
    const float* Vmid_b = (const float*)d_in[8];
    const float* Wihm   = (const float*)d_in[9];
    const float* Whhm   = (const float*)d_in[10];
    const float* bmid   = (const float*)d_in[11];
    const float* Wiht   = (const float*)d_in[12];
    const float* Whht   = (const float*)d_in[13];
    const float* btop   = (const float*)d_in[14];

    conv_ab<<<2048, 256>>>(Wihm, Wiht, Wmid_w);
    gemm_fold_mma<<<dim3(16, 32, 4), 256>>>();
    f0_fold<<<512, 256>>>(Wihm, W0_w);
    gbase_convert<<<2560, 256>>>(Wihm, Wiht, W0_b, Wmid_b, bmid, btop,
                                 V1_w, Vmid_w, Whhm, Whht);
    predcells_kernel<<<NBLK, NTHR>>>(x_seq, V1_b, Vmid_b, (float*)d_out);
}

// round 17
// speedup vs baseline: 1.1435x; 1.0896x over previous
#include <cuda_runtime.h>
#include <cuda_fp16.h>
#include <cuda_fp8.h>

#define TT 256
#define CC 56
#define HH 1024
#define NBLK 148
#define NTHR 1024
#define NBGW 4704                /* bg warps: blocks 1..147 x 32 */
#define INV_WSCALE (1.0f/64.0f)

// ---------------- folded / quantized weights (built per launch) ----------------
__device__ __align__(16) __half  h_F[4][(size_t)4096*1024];   // F_{m->m+1} fp16
__device__ __align__(16) __half  h_F0[(size_t)4096*64];       // Wih0[:,:H]*W0
__device__ __align__(16) unsigned char w8_G[4][(size_t)4096*2048]; // [Wih[:,H:]|Whh] fp8
__device__ __align__(16) unsigned char w8_Gtop[(size_t)4096*1024]; // Whh_top fp8
__device__ __align__(16) __half  h_Vmid[(size_t)4*1024*1024];
__device__ __align__(16) __half  h_V1[(size_t)56*1024];
__device__ float d_gbase[5][4096];

// fp16 staging for the tensor-core fold GEMM
__device__ __align__(16) __half  h_A16[(size_t)4*4096*1024];
__device__ __align__(16) __half  h_BT[(size_t)4*1024*1024];

// ---------------- runtime state ------------------------------------------------
__device__ __align__(16) float g_z[5][4096];   // complete z (F+G), interleaved [k*4+q]
__device__ float g_G[5][4096];                 // G vectors, row-indexed
__device__ __align__(4) __half g_reconR[4][HH];
__device__ __align__(4) __half g_recon1[64];
__device__ float g_loss_parts[TT][5];
__device__ unsigned g_arrive[NBLK];

// ---------------- helpers ------------------------------------------------------
__device__ __forceinline__ float ldf(const float* p) { return __ldcg(p); }
__device__ __forceinline__ void  stf(float* p, float v) { __stcg(p, v); }
__device__ __forceinline__ float ldh(const __half* p) {
    unsigned short u = __ldcg(reinterpret_cast<const unsigned short*>(p));
    return __half2float(__ushort_as_half(u));
}
__device__ __forceinline__ void sth(__half* p, float v) {
    __stcg(reinterpret_cast<unsigned short*>(p), __half_as_ushort(__float2half_rn(v)));
}
__device__ __forceinline__ int il(int r) { return ((r & 1023) << 2) | (r >> 10); }

__device__ __forceinline__ float warp_red(float v) {
#pragma unroll
    for (int o = 16; o; o >>= 1) v += __shfl_xor_sync(0xffffffffu, v, o);
    return v;
}

__device__ __forceinline__ __half2 cvt8(unsigned v16) {
    __half2_raw r = __nv_cvt_fp8x2_to_halfraw2((__nv_fp8x2_storage_t)v16, __NV_E4M3);
    return *reinterpret_cast<__half2*>(&r);
}
__device__ __forceinline__ float hsum(__half2 h) {
    float2 f = __half22float2(h);
    return f.x + f.y;
}

template<int NB>
__device__ __forceinline__ float dot8(const unsigned char* __restrict__ w,
                                      const __half* __restrict__ x, int lane) {
    float acc = 0.f;
#pragma unroll
    for (int it = 0; it < NB / 512; it++) {
        int c = it * 512 + lane * 16;
        uint4 wv  = *reinterpret_cast<const uint4*>(w + c);
        uint4 xv0 = *reinterpret_cast<const uint4*>(reinterpret_cast<const char*>(x) + 2 * c);
        uint4 xv1 = *reinterpret_cast<const uint4*>(reinterpret_cast<const char*>(x) + 2 * c + 16);
        const __half2* xa = reinterpret_cast<const __half2*>(&xv0);
        const __half2* xb = reinterpret_cast<const __half2*>(&xv1);
        __half2 s = __floats2half2_rn(0.f, 0.f);
        s = __hfma2(cvt8(wv.x & 0xffffu), xa[0], s);
        s = __hfma2(cvt8(wv.x >> 16),     xa[1], s);
        s = __hfma2(cvt8(wv.y & 0xffffu), xa[2], s);
        s = __hfma2(cvt8(wv.y >> 16),     xa[3], s);
        s = __hfma2(cvt8(wv.z & 0xffffu), xb[0], s);
        s = __hfma2(cvt8(wv.z >> 16),     xb[1], s);
        s = __hfma2(cvt8(wv.w & 0xffffu), xb[2], s);
        s = __hfma2(cvt8(wv.w >> 16),     xb[3], s);
        acc += hsum(s);
    }
    return acc;
}

template<int NB>
__device__ __forceinline__ float dot16(const __half* __restrict__ w,
                                       const __half* __restrict__ x, int lane) {
    float acc = 0.f;
#pragma unroll
    for (int it = 0; it < NB / 512; it++) {
        int c = it * 512 + lane * 16;
        uint4 wv = *reinterpret_cast<const uint4*>(reinterpret_cast<const char*>(w) + c);
        uint4 xv = *reinterpret_cast<const uint4*>(reinterpret_cast<const char*>(x) + c);
        const __half2* wa = reinterpret_cast<const __half2*>(&wv);
        const __half2* xa = reinterpret_cast<const __half2*>(&xv);
        __half2 s = __floats2half2_rn(0.f, 0.f);
        s = __hfma2(wa[0], xa[0], s);
        s = __hfma2(wa[1], xa[1], s);
        s = __hfma2(wa[2], xa[2], s);
        s = __hfma2(wa[3], xa[3], s);
        acc += hsum(s);
    }
    return acc;
}

__device__ __forceinline__ float dot56h(const __half* __restrict__ w,
                                        const float* __restrict__ x, int lane) {
    float acc = 0.f;
    if (lane < 28) {
        __half2 h = *reinterpret_cast<const __half2*>(w + lane * 2);
        float2 f = __half22float2(h);
        acc = f.x * x[lane * 2] + f.y * x[lane * 2 + 1];
    }
    return acc;
}

__device__ __forceinline__ float sigm(float x) { return 1.f / (1.f + __expf(-x)); }

// ---- split grid barrier: arrive (release) / wait (warp-scan acquire) ----------
__device__ __forceinline__ void bar_arrive(unsigned ep) {
    __syncthreads();
    if (threadIdx.x == 0)
        asm volatile("st.release.gpu.global.b32 [%0], %1;"
                     :: "l"(g_arrive + blockIdx.x), "r"(ep) : "memory");
}
__device__ __forceinline__ void bar_wait(unsigned ep) {
    if (threadIdx.x < 32) {
        const int lane = threadIdx.x;
        bool done = false;
        while (!done) {
            bool ok = true;
#pragma unroll
            for (int j = 0; j < 5; j++) {
                int s = lane + j * 32;
                if (s < NBLK) {
                    unsigned v;
                    asm volatile("ld.acquire.gpu.global.b32 %0, [%1];"
                                 : "=r"(v) : "l"(g_arrive + s) : "memory");
                    ok &= ((int)(v - ep) >= 0);
                }
            }
            done = __all_sync(0xffffffffu, ok);
        }
    }
    __syncthreads();
}

__device__ __forceinline__ float block_sum(float v, float* sred) {
    int lane = threadIdx.x & 31, w = threadIdx.x >> 5;
    v = warp_red(v);
    if (lane == 0) sred[w] = v;
    __syncthreads();
    float r = 0.f;
    if (w == 0) {
        r = (lane < NTHR / 32) ? sred[lane] : 0.f;
        r = warp_red(r);
    }
    __syncthreads();
    return r;
}

// ---------------- pre-pass 0: fp16 staging for the fold GEMM --------------------
__global__ void conv_ab(const float* __restrict__ Wihm, const float* __restrict__ Wiht,
                        const float* __restrict__ Wmid) {
    long i0 = (long)blockIdx.x * blockDim.x + threadIdx.x;
    long st = (long)gridDim.x * blockDim.x;
    for (long i = i0; i < 4L * 4096 * 256; i += st) {
        long zr = i >> 8;
        int z = (int)(zr >> 12);
        long r = zr & 4095;
        int cc = (int)(i & 255) * 4;
        const float* src = (z < 3) ? (Wihm + ((size_t)(z + 1) * 4096 + r) * 2048 + cc)
                                   : (Wiht + (size_t)r * 1024 + cc);
        float4 v = *reinterpret_cast<const float4*>(src);
        *reinterpret_cast<__half2*>(h_A16 + zr * 1024 + cc)     = __floats2half2_rn(v.x, v.y);
        *reinterpret_cast<__half2*>(h_A16 + zr * 1024 + cc + 2) = __floats2half2_rn(v.z, v.w);
    }
    for (long i = i0; i < 4L * 1024 * 1024; i += st) {
        long z = i >> 20;
        int ii = (int)((i >> 10) & 1023);
        int j  = (int)(i & 1023);
        h_BT[z * 1048576 + (size_t)j * 1024 + ii] =
            __float2half_rn(Wmid[z * 1048576 + (size_t)ii * 1024 + j]);
    }
}

// ---------------- pre-pass 1: fold GEMM via mma.sync (HMMA, fp16 out) -----------
__global__ void gemm_fold_mma() {
    const int z = blockIdx.z;
    const __half* A  = h_A16 + (size_t)z * 4096 * 1024;
    const __half* BT = h_BT  + (size_t)z * 1024 * 1024;
    __half* C = &h_F[z][0];
    const int wid = threadIdx.x >> 5, lane = threadIdx.x & 31;
    const int wm = wid >> 1, wn = wid & 1;
    const int m0 = blockIdx.y * 128 + wm * 32;
    const int n0 = blockIdx.x * 64 + wn * 32;
    const int ra = lane >> 2, kc = (lane & 3) * 2;
    float d[2][4][4] = {};
    for (int k0 = 0; k0 < 1024; k0 += 16) {
        unsigned a[2][4], b[4][2];
#pragma unroll
        for (int t = 0; t < 2; t++) {
            const __half* Ab = A + (size_t)(m0 + t * 16 + ra) * 1024 + k0 + kc;
            a[t][0] = *reinterpret_cast<const unsigned*>(Ab);
            a[t][1] = *reinterpret_cast<const unsigned*>(Ab + 8 * 1024);
            a[t][2] = *reinterpret_cast<const unsigned*>(Ab + 8);
            a[t][3] = *reinterpret_cast<const unsigned*>(Ab + 8 * 1024 + 8);
        }
#pragma unroll
        for (int u = 0; u < 4; u++) {
            const __half* Bb = BT + (size_t)(n0 + u * 8 + ra) * 1024 + k0 + kc;
            b[u][0] = *reinterpret_cast<const unsigned*>(Bb);
            b[u][1] = *reinterpret_cast<const unsigned*>(Bb + 8);
        }
#pragma unroll
        for (int t = 0; t < 2; t++)
#pragma unroll
            for (int u = 0; u < 4; u++)
                asm volatile(
                    "mma.sync.aligned.m16n8k16.row.col.f32.f16.f16.f32 "
                    "{%0,%1,%2,%3}, {%4,%5,%6,%7}, {%8,%9}, {%0,%1,%2,%3};"
                    : "+f"(d[t][u][0]), "+f"(d[t][u][1]), "+f"(d[t][u][2]), "+f"(d[t][u][3])
                    : "r"(a[t][0]), "r"(a[t][1]), "r"(a[t][2]), "r"(a[t][3]),
                      "r"(b[u][0]), "r"(b[u][1]));
    }
#pragma unroll
    for (int t = 0; t < 2; t++)
#pragma unroll
        for (int u = 0; u < 4; u++) {
            int r = m0 + t * 16 + ra, c = n0 + u * 8 + kc;
            *reinterpret_cast<__half2*>(C + (size_t)r * 1024 + c) =
                __floats2half2_rn(d[t][u][0], d[t][u][1]);
            *reinterpret_cast<__half2*>(C + (size_t)(r + 8) * 1024 + c) =
                __floats2half2_rn(d[t][u][2], d[t][u][3]);
        }
}

// ---------------- pre-pass 2: F0 = Wih0[:,:H] x W0 ------------------------------
__global__ void f0_fold(const float* __restrict__ Wihm, const float* __restrict__ W0w) {
    int wid = threadIdx.x >> 5, lane = threadIdx.x & 31;
    int r = blockIdx.x * 8 + wid;
    float a[32];
    const float* Arow = Wihm + (size_t)r * 2048;
#pragma unroll
    for (int j = 0; j < 32; j++) a[j] = Arow[lane + 32 * j];
    for (int c = 0; c < CC; c++) {
        float s = 0.f;
#pragma unroll
        for (int j = 0; j < 32; j++) s = fmaf(a[j], W0w[(lane + 32 * j) * CC + c], s);
        s = warp_red(s);
        if (lane == 0) h_F0[(size_t)r * 64 + c] = __float2half_rn(s);
    }
}

// ---------------- pre-pass 3 (merged): gbase + quantize/pack --------------------
__global__ void gbase_convert(const float* __restrict__ Wihm, const float* __restrict__ Wiht,
                              const float* __restrict__ W0_b, const float* __restrict__ Wmid_b,
                              const float* __restrict__ bmid, const float* __restrict__ btop,
                              const float* __restrict__ V1, const float* __restrict__ Vmid,
                              const float* __restrict__ Whhm, const float* __restrict__ Whht) {
    int gwarp = (blockIdx.x * blockDim.x + threadIdx.x) >> 5;
    int lane = threadIdx.x & 31;
    if (gwarp < 5 * 4096) {
        int lay = gwarp >> 12;
        int r = gwarp & 4095;
        const float* Arow;
        const float* bv;
        float bias;
        if (lay < 4) {
            Arow = Wihm + ((size_t)lay * 4096 + r) * 2048;
            bv = (lay == 0) ? W0_b : (Wmid_b + (lay - 1) * 1024);
            bias = bmid[lay * 4096 + r];
        } else {
            Arow = Wiht + (size_t)r * 1024;
            bv = Wmid_b + 3 * 1024;
            bias = btop[r];
        }
        float s = 0.f;
        for (int j = lane; j < 1024; j += 32) s = fmaf(Arow[j], bv[j], s);
        s = warp_red(s);
        if (lane == 0) d_gbase[lay][r] = s + bias;
    }
    long i0 = (long)blockIdx.x * blockDim.x + threadIdx.x;
    long st = (long)gridDim.x * blockDim.x;
#define PACK8(v) ( (unsigned)__nv_cvt_float2_to_fp8x2(make_float2((v).x*64.f,(v).y*64.f), __NV_SATFINITE, __NV_E4M3) \
                 | ((unsigned)__nv_cvt_float2_to_fp8x2(make_float2((v).z*64.f,(v).w*64.f), __NV_SATFINITE, __NV_E4M3) << 16) )
    for (long i = i0; i < 16384L * 256; i += st) {
        long row = i >> 8; int jj = (int)(i & 255) * 4;
        float4 v = *reinterpret_cast<const float4*>(Wihm + row * 2048 + 1024 + jj);
        reinterpret_cast<unsigned*>(&w8_G[0][0])[row * 512 + (jj >> 2)] = PACK8(v);
    }
    for (long i = i0; i < 16384L * 256; i += st) {
        long row = i >> 8; int jj = (int)(i & 255) * 4;
        float4 v = *reinterpret_cast<const float4*>(Whhm + row * 1024 + jj);
        reinterpret_cast<unsigned*>(&w8_G[0][0])[row * 512 + 256 + (jj >> 2)] = PACK8(v);
    }
    for (long i = i0; i < 4096L * 256; i += st) {
        float4 v = *reinterpret_cast<const float4*>(Whht + i * 4);
        reinterpret_cast<unsigned*>(w8_Gtop)[i] = PACK8(v);
    }
#undef PACK8
    for (long i = i0; i < 4L * 1024 * 1024 / 2; i += st)
        reinterpret_cast<__half2*>(h_Vmid)[i] = __float22half2_rn(reinterpret_cast<const float2*>(Vmid)[i]);
    for (long i = i0; i < 56L * 1024 / 2; i += st)
        reinterpret_cast<__half2*>(h_V1)[i] = __float22half2_rn(reinterpret_cast<const float2*>(V1)[i]);
}

// ---------------- main persistent kernel: 2 phases per timestep -----------------
// Layer m of step t is gated at super-phase 2t+m (wavefront schedule).
// Even phase (step t): gates L0(t), L2(t-1), L4(t-2) + same-phase matvecs.
// Odd  phase (step t): gates L1(t), L3(t-1), TD_char(t+1) + same-phase matvecs.
__global__ void __launch_bounds__(NTHR, 1)
predcells_kernel(const float* __restrict__ x_seq,
                 const float* __restrict__ V1_b, const float* __restrict__ Vmid_b,
                 float* __restrict__ out) {
    __shared__ __align__(16) __half s0[2048];   // [TD0|h0](t)
    __shared__ __align__(16) __half s1[2048];   // [TD1|h1](t)
    __shared__ __align__(16) __half s2[2048];   // [TD2|h2](t-1)
    __shared__ __align__(16) __half s3[2048];   // [TD3|h3](t-1)
    __shared__ __align__(16) __half s4[1024];   // h4(t-2)
    __shared__ float sTDc[64];
    __shared__ float sred[32];

    const int tid  = threadIdx.x;
    const int lane = tid & 31;
    const int wid  = tid >> 5;
    const int gw   = blockIdx.x * (NTHR / 32) + wid;
    const int bgw  = gw - 32;                    // bg warp index (blocks 1..147)
    const long gtid = (long)blockIdx.x * NTHR + tid;
    const long gsz  = (long)NBLK * NTHR;

    float c0 = 0.f, c1 = 0.f, c2 = 0.f, c3 = 0.f, c4 = 0.f;
    unsigned ep = g_arrive[blockIdx.x];

    // ---- prologue A: init G=gbase, recons=0; TD_char(0) ----
    for (long i = gtid; i < 5 * 4096; i += gsz) (&g_G[0][0])[i] = (&d_gbase[0][0])[i];
    for (long i = gtid; i < 4 * HH; i += gsz) (&g_reconR[0][0])[i] = __ushort_as_half(0);
    float tdc0 = 0.f;
    if (tid < CC) { tdc0 = fabsf(x_seq[tid]); sTDc[tid] = tdc0; }
    bar_arrive(++ep);
    bar_wait(ep);

    // ---- prologue B: z0(0) = F0c*TDc(0) + G0(0) ----
    if (gw < 4096) {
        float a = warp_red(dot56h(&h_F0[(size_t)gw * 64], sTDc, lane));
        if (lane == 0) stf(&g_z[0][il(gw)], a + ldf(&g_G[0][gw]));
    }
    bar_arrive(++ep);
    if (blockIdx.x == 0) {
        float s = block_sum(tdc0, sred);
        if (tid == 0) stf(&g_loss_parts[0][0], s);
    }
    bar_wait(ep);

    for (int t = 0; t <= 256; t++) {
        // ======================= EVEN phase (2t) ================================
        {
            const bool gl0 = (t <= 255), gl2 = (t >= 1), gl4 = (t >= 2);
            float td0 = 0.f, td2 = 0.f;
            {
                const int k = tid;
                if (gl0) {
                    float4 zv = __ldcg(reinterpret_cast<const float4*>(&g_z[0][k << 2]));
                    float cn = sigm(zv.y) * c0 + sigm(zv.x) * tanhf(zv.z);
                    c0 = cn;
                    float hn = sigm(zv.w) * tanhf(cn);
                    td0 = fabsf(hn - ldh(&g_reconR[0][k]));
                    s0[k] = __float2half_rn(td0);
                    s0[1024 + k] = __float2half_rn(hn);
                }
                if (gl2) {
                    float4 zv = __ldcg(reinterpret_cast<const float4*>(&g_z[2][k << 2]));
                    float cn = sigm(zv.y) * c2 + sigm(zv.x) * tanhf(zv.z);
                    c2 = cn;
                    float hn = sigm(zv.w) * tanhf(cn);
                    td2 = fabsf(hn - ldh(&g_reconR[2][k]));
                    s2[k] = __float2half_rn(td2);
                    s2[1024 + k] = __float2half_rn(hn);
                }
                if (gl4) {
                    float4 zv = __ldcg(reinterpret_cast<const float4*>(&g_z[4][k << 2]));
                    float cn = sigm(zv.y) * c4 + sigm(zv.x) * tanhf(zv.z);
                    c4 = cn;
                    s4[k] = __float2half_rn(sigm(zv.w) * tanhf(cn));
                }
            }
            __syncthreads();
            if (blockIdx.x > 0) {
                for (int task = bgw; task < 22584; task += NBGW) {
                    if (task < 4096) {                       // z1(t) = F0*TD0 + G1(t)
                        if (gl0) {
                            int r = task;
                            float a = warp_red(dot16<2048>(&h_F[0][(size_t)r * 1024], s0, lane));
                            if (lane == 0) stf(&g_z[1][il(r)], a + ldf(&g_G[1][r]));
                        }
                    } else if (task < 8192) {                // G0(t+1) from [TD0|h0](t)
                        if (gl0) {
                            int r = task - 4096;
                            float a = warp_red(dot8<2048>(&w8_G[0][(size_t)r * 2048], s0, lane));
                            if (lane == 0) stf(&g_G[0][r], a * INV_WSCALE + d_gbase[0][r]);
                        }
                    } else if (task < 12288) {               // z3(t-1) = F2*TD2 + G3(t-1)
                        if (gl2) {
                            int r = task - 8192;
                            float a = warp_red(dot16<2048>(&h_F[2][(size_t)r * 1024], s2, lane));
                            if (lane == 0) stf(&g_z[3][il(r)], a + ldf(&g_G[3][r]));
                        }
                    } else if (task < 16384) {               // G2(t) from [TD2|h2](t-1)
                        if (gl2 && t <= 255) {
                            int r = task - 12288;
                            float a = warp_red(dot8<2048>(&w8_G[2][(size_t)r * 2048], s2, lane));
                            if (lane == 0) stf(&g_G[2][r], a * INV_WSCALE + d_gbase[2][r]);
                        }
                    } else if (task < 20480) {               // Gtop(t-1) from h4(t-2)
                        if (gl4) {
                            int r = task - 16384;
                            float a = warp_red(dot8<1024>(w8_Gtop + (size_t)r * 1024, s4, lane));
                            if (lane == 0) stf(&g_G[4][r], a * INV_WSCALE + d_gbase[4][r]);
                        }
                    } else if (task < 21504) {               // reconR[1](t-1) = Vmid1*h2(t-1)
                        if (gl2) {
                            int v = task - 20480;
                            float a = warp_red(dot16<2048>(h_Vmid + 1048576 + (size_t)v * 1024, s2 + 1024, lane));
                            if (lane == 0) sth(&g_reconR[1][v], a + Vmid_b[1024 + v]);
                        }
                    } else if (task < 22528) {               // reconR[3](t-2) = Vmid3*h4(t-2)
                        if (gl4) {
                            int v = task - 21504;
                            float a = warp_red(dot16<2048>(h_Vmid + (size_t)3 * 1048576 + (size_t)v * 1024, s4, lane));
                            if (lane == 0) sth(&g_reconR[3][v], a + Vmid_b[3072 + v]);
                        }
                    } else {                                 // recon1(t) = V1*h0(t)
                        if (gl0) {
                            int v = task - 22528;
                            float a = warp_red(dot16<2048>(h_V1 + (size_t)v * 1024, s0 + 1024, lane));
                            if (lane == 0) sth(&g_recon1[v], a + V1_b[v]);
                        }
                    }
                }
            }
            bar_arrive(++ep);
            if (blockIdx.x == 0) {
                if (gl0) {
                    float s = block_sum(td0, sred);
                    if (tid == 0) stf(&g_loss_parts[t][1], s);
                }
                if (gl2) {
                    float s = block_sum(td2, sred);
                    if (tid == 0) stf(&g_loss_parts[t - 1][3], s);
                }
            }
            bar_wait(ep);
        }

        // ======================= ODD phase (2t+1) ================================
        {
            const bool gl1 = (t <= 255), gl3 = (t >= 1), glc = (t <= 254);
            float td1 = 0.f, td3 = 0.f, tdc = 0.f;
            {
                const int k = tid;
                if (gl1) {
                    float4 zv = __ldcg(reinterpret_cast<const float4*>(&g_z[1][k << 2]));
                    float cn = sigm(zv.y) * c1 + sigm(zv.x) * tanhf(zv.z);
                    c1 = cn;
                    float hn = sigm(zv.w) * tanhf(cn);
                    td1 = fabsf(hn - ldh(&g_reconR[1][k]));
                    s1[k] = __float2half_rn(td1);
                    s1[1024 + k] = __float2half_rn(hn);
                }
                if (gl3) {
                    float4 zv = __ldcg(reinterpret_cast<const float4*>(&g_z[3][k << 2]));
                    float cn = sigm(zv.y) * c3 + sigm(zv.x) * tanhf(zv.z);
                    c3 = cn;
                    float hn = sigm(zv.w) * tanhf(cn);
                    td3 = fabsf(hn - ldh(&g_reconR[3][k]));
                    s3[k] = __float2half_rn(td3);
                    s3[1024 + k] = __float2half_rn(hn);
                }
                if (glc && tid < CC) {
                    tdc = fabsf(x_seq[(t + 1) * CC + tid] - ldh(&g_recon1[tid]));
                    sTDc[tid] = tdc;
                }
            }
            __syncthreads();
            if (blockIdx.x > 0) {
                for (int task = bgw; task < 22528; task += NBGW) {
                    if (task < 4096) {                       // z2(t) = F1*TD1 + G2(t)
                        if (gl1) {
                            int r = task;
                            float a = warp_red(dot16<2048>(&h_F[1][(size_t)r * 1024], s1, lane));
                            if (lane == 0) stf(&g_z[2][il(r)], a + ldf(&g_G[2][r]));
                        }
                    } else if (task < 8192) {                // G1(t+1) from [TD1|h1](t)
                        if (gl1) {
                            int r = task - 4096;
                            float a = warp_red(dot8<2048>(&w8_G[1][(size_t)r * 2048], s1, lane));
                            if (lane == 0) stf(&g_G[1][r], a * INV_WSCALE + d_gbase[1][r]);
                        }
                    } else if (task < 12288) {               // z4(t-1) = F3*TD3 + Gtop(t-1)
                        if (gl3) {
                            int r = task - 8192;
                            float a = warp_red(dot16<2048>(&h_F[3][(size_t)r * 1024], s3, lane));
                            if (lane == 0) stf(&g_z[4][il(r)], a + ldf(&g_G[4][r]));
                        }
                    } else if (task < 16384) {               // G3(t) from [TD3|h3](t-1)
                        if (gl3 && t <= 255) {
                            int r = task - 12288;
                            float a = warp_red(dot8<2048>(&w8_G[3][(size_t)r * 2048], s3, lane));
                            if (lane == 0) stf(&g_G[3][r], a * INV_WSCALE + d_gbase[3][r]);
                        }
                    } else if (task < 20480) {               // z0(t+1) = F0c*TDc(t+1) + G0(t+1)
                        if (glc) {
                            int r = task - 16384;
                            float a = warp_red(dot56h(&h_F0[(size_t)r * 64], sTDc, lane));
                            if (lane == 0) stf(&g_z[0][il(r)], a + ldf(&g_G[0][r]));
                        }
                    } else if (task < 21504) {               // reconR[0](t) = Vmid0*h1(t)
                        if (gl1) {
                            int v = task - 20480;
                            float a = warp_red(dot16<2048>(h_Vmid + (size_t)v * 1024, s1 + 1024, lane));
                            if (lane == 0) sth(&g_reconR[0][v], a + Vmid_b[v]);
                        }
                    } else {                                 // reconR[2](t-1) = Vmid2*h3(t-1)
                        if (gl3) {
                            int v = task - 21504;
                            float a = warp_red(dot16<2048>(h_Vmid + (size_t)2 * 1048576 + (size_t)v * 1024, s3 + 1024, lane));
                            if (lane == 0) sth(&g_reconR[2][v], a + Vmid_b[2048 + v]);
                        }
                    }
                }
            }
            bar_arrive(++ep);
            if (blockIdx.x == 0) {
                if (gl1) {
                    float s = block_sum(td1, sred);
                    if (tid == 0) stf(&g_loss_parts[t][2], s);
                }
                if (gl3) {
                    float s = block_sum(td3, sred);
                    if (tid == 0) stf(&g_loss_parts[t - 1][4], s);
                }
                if (glc) {
                    float s = block_sum(tdc, sred);
                    if (tid == 0) stf(&g_loss_parts[t + 1][0], s);
                }
            }
            bar_wait(ep);
        }
    }

    // ---- epilogue: deterministic loss reduction ----
    if (blockIdx.x == 0) {
        const float* parts = &g_loss_parts[0][0];
        float v = 0.f;
        for (int i = tid; i < TT * 5; i += NTHR) v += ldf(&parts[i]);
        float s = block_sum(v, sred);
        if (tid == 0) out[0] = s;
    }
}

// ---------------- launch ----------------------------------------------------------
extern "C" void kernel_launch(void* const* d_in, const int* in_sizes, int n_in,
                              void* d_out, int out_size) {
    (void)in_sizes; (void)n_in; (void)out_size;
    const float* x_seq  = (const float*)d_in[0];
    const float* W0_w   = (const float*)d_in[1];
    const float* W0_b   = (const float*)d_in[2];
    const float* Wmid_w = (const float*)d_in[3];
    const float* Wmid_b = (const float*)d_in[4];
    const float* V1_w   = (const float*)d_in[5];
    const float* V1_b   = (const float*)d_in[6];
    const float* Vmid_w = (const float*)d_in[7];
    const float* Vmid_b = (const float*)d_in[8];
    const float* Wihm   = (const float*)d_in[9];
    const float* Whhm   = (const float*)d_in[10];
    const float* bmid   = (const float*)d_in[11];
    const float* Wiht   = (const float*)d_in[12];
    const float* Whht   = (const float*)d_in[13];
    const float* btop   = (const float*)d_in[14];

    conv_ab<<<2048, 256>>>(Wihm, Wiht, Wmid_w);
    gemm_fold_mma<<<dim3(16, 32, 4), 256>>>();
    f0_fold<<<512, 256>>>(Wihm, W0_w);
    gbase_convert<<<2560, 256>>>(Wihm, Wiht, W0_b, Wmid_b, bmid, btop,
                                 V1_w, Vmid_w, Whhm, Whht);
    predcells_kernel<<<NBLK, NTHR>>>(x_seq, V1_b, Vmid_b, (float*)d_out);
}